// round 6
// baseline (speedup 1.0000x reference)
#include <cuda_runtime.h>
#include <cuda_bf16.h>

#define D_MODEL 768
#define NTOK 4096           // B*S = 2*2048
#define SEQ 2048
#define NHEAD 12
#define HDIM 64
#define LORA_R 16
#define LORA_SCALE 4.0f     // U * alpha/sqrt(R) = 1.0 * 16/4

typedef unsigned long long ull;

// ---------------- packed fp32x2 helpers (exact IEEE fp32, 2x rate) ---------
__device__ __forceinline__ ull pk2(float lo, float hi) {
    ull r;
    asm("mov.b64 %0, {%1, %2};" : "=l"(r)
        : "r"(__float_as_uint(lo)), "r"(__float_as_uint(hi)));
    return r;
}
__device__ __forceinline__ void fma2(ull& d, ull a, ull b) {
    asm("fma.rn.f32x2 %0, %1, %2, %0;" : "+l"(d) : "l"(a), "l"(b));
}
__device__ __forceinline__ void mul2(ull& d, ull a, ull b) {
    asm("mul.rn.f32x2 %0, %1, %2;" : "=l"(d) : "l"(a), "l"(b));
}
__device__ __forceinline__ float2 upk2(ull v) {
    unsigned lo, hi;
    asm("mov.b64 {%0, %1}, %2;" : "=r"(lo), "=r"(hi) : "l"(v));
    return make_float2(__uint_as_float(lo), __uint_as_float(hi));
}
__device__ __forceinline__ float fexp2(float x) {
    float r;
    asm("ex2.approx.ftz.f32 %0, %1;" : "=f"(r) : "f"(x));
    return r;
}

// ---------------- scratch (device globals: no allocation allowed) ----------
__device__ float g_Mq[D_MODEL * D_MODEL];
__device__ float g_Mk[D_MODEL * D_MODEL];
__device__ float g_Mv[D_MODEL * D_MODEL];
__device__ float g_Mo[D_MODEL * D_MODEL];
__device__ float g_q[NTOK * D_MODEL];
__device__ float g_k[NTOK * D_MODEL];
__device__ float g_v[NTOK * D_MODEL];
__device__ float g_ao[NTOK * D_MODEL];

// ---------------- build all 4 effective weights in ONE launch --------------
__global__ void build_weight4_kernel(const float* __restrict__ Wq,
                                     const float* __restrict__ Aq,
                                     const float* __restrict__ Wk,
                                     const float* __restrict__ Ak,
                                     const float* __restrict__ Wv,
                                     const float* __restrict__ Av,
                                     const float* __restrict__ Wo,
                                     float* __restrict__ Mq,
                                     float* __restrict__ Mk,
                                     float* __restrict__ Mv,
                                     float* __restrict__ Mo) {
    int which = blockIdx.y;
    const float* W = (which == 0) ? Wq : (which == 1) ? Wk : (which == 2) ? Wv : Wo;
    const float* A = (which == 0) ? Aq : (which == 1) ? Ak : Av;
    float* M = (which == 0) ? Mq : (which == 1) ? Mk : (which == 2) ? Mv : Mo;
    float scale = (which == 3) ? 0.0f : LORA_SCALE;

    int idx = blockIdx.x * blockDim.x + threadIdx.x;
    if (idx >= D_MODEL * D_MODEL) return;
    int i = idx / D_MODEL;
    int j = idx - i * D_MODEL;
    float acc = W[j * D_MODEL + i];
    if (scale != 0.0f) {
        float s = 0.0f;
#pragma unroll
        for (int r = 0; r < LORA_R; r++)
            s += A[i * LORA_R + r] * A[j * LORA_R + r];
        acc += scale * s;
    }
    M[idx] = acc;
}

// ---------------- SGEMM x3 (z-batched): Y = X*Mw + bias --------------------
__global__ __launch_bounds__(256, 2) void sgemm3_kernel(
    const float* __restrict__ X0, const float* __restrict__ X1, const float* __restrict__ X2,
    const float* __restrict__ M0, const float* __restrict__ M1, const float* __restrict__ M2,
    const float* __restrict__ B0, const float* __restrict__ B1, const float* __restrict__ B2,
    float* __restrict__ Y0, float* __restrict__ Y1, float* __restrict__ Y2) {
    const int N = D_MODEL, K = D_MODEL;
    int z = blockIdx.z;
    const float* X    = (z == 0) ? X0 : (z == 1) ? X1 : X2;
    const float* Mw   = (z == 0) ? M0 : (z == 1) ? M1 : M2;
    const float* bias = (z == 0) ? B0 : (z == 1) ? B1 : B2;
    float* Y          = (z == 0) ? Y0 : (z == 1) ? Y1 : Y2;

    __shared__ float As[2][16][128];   // [buf][k][m]
    __shared__ float Bs[2][16][128];   // [buf][k][n]

    int tid  = threadIdx.x;
    int brow = blockIdx.y * 128;
    int bcol = blockIdx.x * 128;
    int tr = tid >> 4;
    int tc = tid & 15;

    int am = tid >> 1;
    int ak = (tid & 1) * 8;
    int bk = tid >> 5;
    int bn = (tid & 31) * 4;

    const float* Xp  = X  + (size_t)(brow + am) * K + ak;
    const float* Bp0 = Mw + (size_t)bk * N + bcol + bn;
    const float* Bp1 = Mw + (size_t)(bk + 8) * N + bcol + bn;

    ull acc[8][4];
#pragma unroll
    for (int i = 0; i < 8; i++)
#pragma unroll
        for (int j = 0; j < 4; j++) acc[i][j] = 0ULL;

    float4 a0v = *reinterpret_cast<const float4*>(Xp);
    float4 a1v = *reinterpret_cast<const float4*>(Xp + 4);
    float4 b0v = *reinterpret_cast<const float4*>(Bp0);
    float4 b1v = *reinterpret_cast<const float4*>(Bp1);
    As[0][ak + 0][am] = a0v.x; As[0][ak + 1][am] = a0v.y;
    As[0][ak + 2][am] = a0v.z; As[0][ak + 3][am] = a0v.w;
    As[0][ak + 4][am] = a1v.x; As[0][ak + 5][am] = a1v.y;
    As[0][ak + 6][am] = a1v.z; As[0][ak + 7][am] = a1v.w;
    *reinterpret_cast<float4*>(&Bs[0][bk][bn])     = b0v;
    *reinterpret_cast<float4*>(&Bs[0][bk + 8][bn]) = b1v;
    __syncthreads();

    int buf = 0;
    for (int k0 = 0; k0 < K; k0 += 16) {
        bool has = (k0 + 16) < K;
        if (has) {
            a0v = *reinterpret_cast<const float4*>(Xp + k0 + 16);
            a1v = *reinterpret_cast<const float4*>(Xp + k0 + 20);
            b0v = *reinterpret_cast<const float4*>(Bp0 + (size_t)(k0 + 16) * N);
            b1v = *reinterpret_cast<const float4*>(Bp1 + (size_t)(k0 + 16) * N);
        }
#pragma unroll
        for (int kk = 0; kk < 16; kk++) {
            float4 af0 = *reinterpret_cast<const float4*>(&As[buf][kk][tr * 8]);
            float4 af1 = *reinterpret_cast<const float4*>(&As[buf][kk][tr * 8 + 4]);
            ulonglong2 bl = *reinterpret_cast<const ulonglong2*>(&Bs[buf][kk][tc * 8]);
            ulonglong2 bh = *reinterpret_cast<const ulonglong2*>(&Bs[buf][kk][tc * 8 + 4]);
            float afs[8] = {af0.x, af0.y, af0.z, af0.w, af1.x, af1.y, af1.z, af1.w};
#pragma unroll
            for (int i = 0; i < 8; i++) {
                ull da = pk2(afs[i], afs[i]);
                fma2(acc[i][0], da, bl.x);
                fma2(acc[i][1], da, bl.y);
                fma2(acc[i][2], da, bh.x);
                fma2(acc[i][3], da, bh.y);
            }
        }
        if (has) {
            As[buf ^ 1][ak + 0][am] = a0v.x; As[buf ^ 1][ak + 1][am] = a0v.y;
            As[buf ^ 1][ak + 2][am] = a0v.z; As[buf ^ 1][ak + 3][am] = a0v.w;
            As[buf ^ 1][ak + 4][am] = a1v.x; As[buf ^ 1][ak + 5][am] = a1v.y;
            As[buf ^ 1][ak + 6][am] = a1v.z; As[buf ^ 1][ak + 7][am] = a1v.w;
            *reinterpret_cast<float4*>(&Bs[buf ^ 1][bk][bn])     = b0v;
            *reinterpret_cast<float4*>(&Bs[buf ^ 1][bk + 8][bn]) = b1v;
        }
        __syncthreads();
        buf ^= 1;
    }

#pragma unroll
    for (int i = 0; i < 8; i++) {
        size_t row = brow + tr * 8 + i;
        int col = bcol + tc * 8;
        float2 p0 = upk2(acc[i][0]), p1 = upk2(acc[i][1]);
        float2 p2 = upk2(acc[i][2]), p3 = upk2(acc[i][3]);
        float4 o0, o1;
        o0.x = p0.x + bias[col + 0]; o0.y = p0.y + bias[col + 1];
        o0.z = p1.x + bias[col + 2]; o0.w = p1.y + bias[col + 3];
        o1.x = p2.x + bias[col + 4]; o1.y = p2.y + bias[col + 5];
        o1.z = p3.x + bias[col + 6]; o1.w = p3.y + bias[col + 7];
        *reinterpret_cast<float4*>(&Y[row * N + col])     = o0;
        *reinterpret_cast<float4*>(&Y[row * N + col + 4]) = o1;
    }
}

// ---------------- attention v3: 3 CTAs/SM, 2-pass scores -------------------
#define AST 68
#define ATT_SMEM (4 * 64 * AST * 4)
#define QSCALE (0.125f * 1.4426950408889634f)   // 1/sqrt(64) * log2(e)

__global__ __launch_bounds__(256, 3) void attn_kernel(
    const float* __restrict__ q, const float* __restrict__ k,
    const float* __restrict__ v, float* __restrict__ o) {
    extern __shared__ float sm[];
    float* Qs = sm;                 // [64][AST], pre-scaled by QSCALE
    float* Ks = sm + 64 * AST;      // [64][AST] row-major (key, d)
    float* Vs = Ks + 64 * AST;      // [64][AST] row-major (key, d)
    float* Ss = Vs + 64 * AST;      // [64][AST] scores -> probs

    int qt = blockIdx.x;
    int bh = blockIdx.y;
    int b = bh / NHEAD;
    int h = bh - b * NHEAD;
    size_t base = (size_t)b * SEQ * D_MODEL + (size_t)h * HDIM;

    int tid = threadIdx.x;
    int lr = tid >> 2;               // row (softmax/PV/load)
    int lc = (tid & 3) * 16;         // col segment
    int sr = (tid >> 4) * 4;         // score rows
    int tc = tid & 15;               // score col base

    // load Q tile (fold softmax scale + log2e)
    {
        const float* src = q + base + (size_t)(qt * 64 + lr) * D_MODEL + lc;
        float4* dst = reinterpret_cast<float4*>(&Qs[lr * AST + lc]);
#pragma unroll
        for (int i = 0; i < 4; i++) {
            float4 qv = reinterpret_cast<const float4*>(src)[i];
            qv.x *= QSCALE; qv.y *= QSCALE; qv.z *= QSCALE; qv.w *= QSCALE;
            dst[i] = qv;
        }
    }

    float m = -1e30f, l = 0.0f;
    ull oacc[8];
#pragma unroll
    for (int i = 0; i < 8; i++) oacc[i] = 0ULL;

    for (int kt0 = 0; kt0 < SEQ; kt0 += 64) {
        // load K and V row-major (no transpose)
        {
            const float* ksrc = k + base + (size_t)(kt0 + lr) * D_MODEL + lc;
            const float* vsrc = v + base + (size_t)(kt0 + lr) * D_MODEL + lc;
            float4* kdst = reinterpret_cast<float4*>(&Ks[lr * AST + lc]);
            float4* vdst = reinterpret_cast<float4*>(&Vs[lr * AST + lc]);
#pragma unroll
            for (int i = 0; i < 4; i++) {
                kdst[i] = reinterpret_cast<const float4*>(ksrc)[i];
                vdst[i] = reinterpret_cast<const float4*>(vsrc)[i];
            }
        }
        __syncthreads();

        // scores: 4 rows x 4 strided cols per thread, 2 col-group passes
        // (halved live accumulators so 3 CTAs/SM fit the register budget)
#pragma unroll
        for (int half = 0; half < 2; half++) {
            ull sacc[4][2];
#pragma unroll
            for (int i = 0; i < 4; i++) { sacc[i][0] = 0ULL; sacc[i][1] = 0ULL; }
            int c0 = tc + 32 * half;       // cols c0 and c0+16
#pragma unroll 4
            for (int d0 = 0; d0 < 64; d0 += 4) {
                ulonglong2 kp0 = *reinterpret_cast<const ulonglong2*>(&Ks[c0 * AST + d0]);
                ulonglong2 kp1 = *reinterpret_cast<const ulonglong2*>(&Ks[(c0 + 16) * AST + d0]);
#pragma unroll
                for (int i = 0; i < 4; i++) {
                    ulonglong2 qp = *reinterpret_cast<const ulonglong2*>(&Qs[(sr + i) * AST + d0]);
                    fma2(sacc[i][0], qp.x, kp0.x);
                    fma2(sacc[i][0], qp.y, kp0.y);
                    fma2(sacc[i][1], qp.x, kp1.x);
                    fma2(sacc[i][1], qp.y, kp1.y);
                }
            }
#pragma unroll
            for (int i = 0; i < 4; i++) {
                float2 t0 = upk2(sacc[i][0]);
                float2 t1 = upk2(sacc[i][1]);
                Ss[(sr + i) * AST + c0]      = t0.x + t0.y;
                Ss[(sr + i) * AST + c0 + 16] = t1.x + t1.y;
            }
        }
        __syncthreads();

        // online softmax: quad covers the 64 cols of row lr
        {
            float* srow = &Ss[lr * AST + lc];
            float s[16];
#pragma unroll
            for (int i = 0; i < 4; i++) {
                float4 sv = *reinterpret_cast<const float4*>(&srow[4 * i]);
                s[4 * i] = sv.x; s[4 * i + 1] = sv.y;
                s[4 * i + 2] = sv.z; s[4 * i + 3] = sv.w;
            }
            float rmax = s[0];
#pragma unroll
            for (int i = 1; i < 16; i++) rmax = fmaxf(rmax, s[i]);
            rmax = fmaxf(rmax, __shfl_xor_sync(0xffffffffu, rmax, 1));
            rmax = fmaxf(rmax, __shfl_xor_sync(0xffffffffu, rmax, 2));
            float newm = fmaxf(m, rmax);
            float alpha = fexp2(m - newm);
            m = newm;
            float rsum = 0.0f;
#pragma unroll
            for (int i = 0; i < 16; i++) {
                s[i] = fexp2(s[i] - newm);
                rsum += s[i];
            }
            rsum += __shfl_xor_sync(0xffffffffu, rsum, 1);
            rsum += __shfl_xor_sync(0xffffffffu, rsum, 2);
            l = l * alpha + rsum;
#pragma unroll
            for (int i = 0; i < 4; i++) {
                float4 pv = make_float4(s[4 * i], s[4 * i + 1], s[4 * i + 2], s[4 * i + 3]);
                *reinterpret_cast<float4*>(&srow[4 * i]) = pv;
            }
            ull ad = pk2(alpha, alpha);
#pragma unroll
            for (int i = 0; i < 8; i++) mul2(oacc[i], oacc[i], ad);
        }
        __syncwarp();

        // PV: oacc[row lr][cols lc..lc+15] += p[lr][j] * V[j][cols]
        {
            const float* prow = &Ss[lr * AST];
#pragma unroll 2
            for (int j0 = 0; j0 < 64; j0 += 4) {
                float4 p4 = *reinterpret_cast<const float4*>(&prow[j0]);
                float ps[4] = {p4.x, p4.y, p4.z, p4.w};
#pragma unroll
                for (int jj = 0; jj < 4; jj++) {
                    ull pd = pk2(ps[jj], ps[jj]);
                    const ulonglong2* vp =
                        reinterpret_cast<const ulonglong2*>(&Vs[(j0 + jj) * AST + lc]);
                    ulonglong2 v0 = vp[0];
                    ulonglong2 v1 = vp[1];
                    fma2(oacc[0], pd, v0.x);
                    fma2(oacc[1], pd, v0.y);
                    fma2(oacc[2], pd, v1.x);
                    fma2(oacc[3], pd, v1.y);
                    ulonglong2 v2 = vp[2];
                    ulonglong2 v3 = vp[3];
                    fma2(oacc[4], pd, v2.x);
                    fma2(oacc[5], pd, v2.y);
                    fma2(oacc[6], pd, v3.x);
                    fma2(oacc[7], pd, v3.y);
                }
            }
        }
        __syncthreads();
    }

    float inv = 1.0f / l;
    float* dst = o + base + (size_t)(qt * 64 + lr) * D_MODEL + lc;
#pragma unroll
    for (int i = 0; i < 4; i++) {
        float2 p0 = upk2(oacc[2 * i + 0]);
        float2 p1 = upk2(oacc[2 * i + 1]);
        float4 ov = make_float4(p0.x * inv, p0.y * inv, p1.x * inv, p1.y * inv);
        reinterpret_cast<float4*>(dst)[i] = ov;
    }
}

// ---------------- launch ---------------------------------------------------
extern "C" void kernel_launch(void* const* d_in, const int* in_sizes, int n_in,
                              void* d_out, int out_size) {
    const float* query = (const float*)d_in[0];
    const float* key_  = (const float*)d_in[1];
    const float* value = (const float*)d_in[2];
    const float* Wq = (const float*)d_in[3];
    const float* bq = (const float*)d_in[4];
    const float* Aq = (const float*)d_in[5];
    const float* Wk = (const float*)d_in[6];
    const float* bk = (const float*)d_in[7];
    const float* Ak = (const float*)d_in[8];
    const float* Wv = (const float*)d_in[9];
    const float* bv = (const float*)d_in[10];
    const float* Av = (const float*)d_in[11];
    const float* Wo = (const float*)d_in[12];
    const float* bo = (const float*)d_in[13];
    float* out = (float*)d_out;

    float *pMq, *pMk, *pMv, *pMo, *pq, *pk, *pv, *pao;
    cudaGetSymbolAddress((void**)&pMq, g_Mq);
    cudaGetSymbolAddress((void**)&pMk, g_Mk);
    cudaGetSymbolAddress((void**)&pMv, g_Mv);
    cudaGetSymbolAddress((void**)&pMo, g_Mo);
    cudaGetSymbolAddress((void**)&pq, g_q);
    cudaGetSymbolAddress((void**)&pk, g_k);
    cudaGetSymbolAddress((void**)&pv, g_v);
    cudaGetSymbolAddress((void**)&pao, g_ao);

    cudaFuncSetAttribute(attn_kernel,
                         cudaFuncAttributeMaxDynamicSharedMemorySize, ATT_SMEM);

    int nw = D_MODEL * D_MODEL;
    dim3 bgrid((nw + 255) / 256, 4);
    build_weight4_kernel<<<bgrid, 256>>>(Wq, Aq, Wk, Ak, Wv, Av, Wo,    // #0
                                         pMq, pMk, pMv, pMo);

    dim3 ggrid(D_MODEL / 128, NTOK / 128, 3);                           // #1
    sgemm3_kernel<<<ggrid, 256>>>(query, key_, value,
                                  pMq, pMk, pMv,
                                  bq, bk, bv,
                                  pq, pk, pv);

    dim3 agrid(SEQ / 64, 2 * NHEAD);                                    // #2 (profiled)
    attn_kernel<<<agrid, 256, ATT_SMEM>>>(pq, pk, pv, pao);

    dim3 ogrid(D_MODEL / 128, NTOK / 128, 1);                           // #3
    sgemm3_kernel<<<ogrid, 256>>>(pao, pao, pao,
                                  pMo, pMo, pMo,
                                  bo, bo, bo,
                                  out, out, out);
}

// round 8
// speedup vs baseline: 1.1429x; 1.1429x over previous
#include <cuda_runtime.h>
#include <cuda_bf16.h>
#include <cstdint>

#define D_MODEL 768
#define NTOK 4096           // B*S = 2*2048
#define SEQ 2048
#define NHEAD 12
#define LORA_R 16
#define LORA_SCALE 4.0f

typedef unsigned long long ull;
typedef __nv_bfloat16 bf16;

// ---------------- packed fp32x2 + misc helpers -----------------------------
__device__ __forceinline__ ull pk2(float lo, float hi) {
    ull r;
    asm("mov.b64 %0, {%1, %2};" : "=l"(r)
        : "r"(__float_as_uint(lo)), "r"(__float_as_uint(hi)));
    return r;
}
__device__ __forceinline__ void fma2(ull& d, ull a, ull b) {
    asm("fma.rn.f32x2 %0, %1, %2, %0;" : "+l"(d) : "l"(a), "l"(b));
}
__device__ __forceinline__ void mul2(ull& d, ull a, ull b) {
    asm("mul.rn.f32x2 %0, %1, %2;" : "=l"(d) : "l"(a), "l"(b));
}
__device__ __forceinline__ float2 upk2(ull v) {
    unsigned lo, hi;
    asm("mov.b64 {%0, %1}, %2;" : "=r"(lo), "=r"(hi) : "l"(v));
    return make_float2(__uint_as_float(lo), __uint_as_float(hi));
}
__device__ __forceinline__ float fexp2(float x) {
    float r;
    asm("ex2.approx.ftz.f32 %0, %1;" : "=f"(r) : "f"(x));
    return r;
}
__device__ __forceinline__ uint32_t smem_u32(const void* p) {
    uint32_t a;
    asm("{ .reg .u64 t; cvta.to.shared.u64 t, %1; cvt.u32.u64 %0, t; }"
        : "=r"(a) : "l"(p));
    return a;
}

// ---------------- warp MMA primitives (baseline PTX, works on sm_103) ------
__device__ __forceinline__ void ldm_x4(uint32_t* f, uint32_t addr) {
    asm volatile("ldmatrix.sync.aligned.m8n8.x4.shared.b16 {%0,%1,%2,%3}, [%4];"
                 : "=r"(f[0]), "=r"(f[1]), "=r"(f[2]), "=r"(f[3]) : "r"(addr));
}
__device__ __forceinline__ void ldm_x2(uint32_t* f, uint32_t addr) {
    asm volatile("ldmatrix.sync.aligned.m8n8.x2.shared.b16 {%0,%1}, [%2];"
                 : "=r"(f[0]), "=r"(f[1]) : "r"(addr));
}
__device__ __forceinline__ void mma_bf16(float* c, const uint32_t* a, const uint32_t* b) {
    asm volatile(
        "mma.sync.aligned.m16n8k16.row.col.f32.bf16.bf16.f32 "
        "{%0,%1,%2,%3}, {%4,%5,%6,%7}, {%8,%9}, {%0,%1,%2,%3};"
        : "+f"(c[0]), "+f"(c[1]), "+f"(c[2]), "+f"(c[3])
        : "r"(a[0]), "r"(a[1]), "r"(a[2]), "r"(a[3]), "r"(b[0]), "r"(b[1]));
}

// ---------------- scratch ---------------------------------------------------
__device__ bf16 g_wh[4 * D_MODEL * D_MODEL];
__device__ bf16 g_wl[4 * D_MODEL * D_MODEL];
__device__ bf16 g_xh[3 * NTOK * D_MODEL];
__device__ bf16 g_xl[3 * NTOK * D_MODEL];
__device__ float g_q[NTOK * D_MODEL];
__device__ float g_k[NTOK * D_MODEL];
__device__ float g_v[NTOK * D_MODEL];
__device__ float g_ao[NTOK * D_MODEL];

// ---------------- weight build + bf16 split: B[n][k] = W[n][k] + s<A_n,A_k> -
__global__ void wsplit_kernel(const float* __restrict__ Wq, const float* __restrict__ Aq,
                              const float* __restrict__ Wk, const float* __restrict__ Ak,
                              const float* __restrict__ Wv, const float* __restrict__ Av,
                              const float* __restrict__ Wo,
                              bf16* __restrict__ wh, bf16* __restrict__ wl) {
    int which = blockIdx.y;
    const float* W = (which == 0) ? Wq : (which == 1) ? Wk : (which == 2) ? Wv : Wo;
    const float* A = (which == 0) ? Aq : (which == 1) ? Ak : Av;
    int idx = blockIdx.x * blockDim.x + threadIdx.x;
    if (idx >= D_MODEL * D_MODEL) return;
    int n = idx / D_MODEL;
    int k = idx - n * D_MODEL;
    float acc = W[idx];                     // row-major W[n][k] — no transpose needed
    if (which < 3) {
        float s = 0.0f;
#pragma unroll
        for (int r = 0; r < LORA_R; r++)
            s += A[n * LORA_R + r] * A[k * LORA_R + r];
        acc += LORA_SCALE * s;
    }
    bf16 h = __float2bfloat16(acc);
    bf16 l = __float2bfloat16(acc - __bfloat162float(h));
    size_t o = (size_t)which * D_MODEL * D_MODEL + idx;
    wh[o] = h;
    wl[o] = l;
}

// ---------------- activation bf16 split (z-batched over up to 3 tensors) ---
__global__ void xsplit_kernel(const float* __restrict__ x0,
                              const float* __restrict__ x1,
                              const float* __restrict__ x2,
                              bf16* __restrict__ h, bf16* __restrict__ l) {
    int z = blockIdx.z;
    const float* x = (z == 0) ? x0 : (z == 1) ? x1 : x2;
    size_t i = ((size_t)blockIdx.x * blockDim.x + threadIdx.x) * 4;
    if (i >= (size_t)NTOK * D_MODEL) return;
    size_t o = (size_t)z * NTOK * D_MODEL + i;
    float4 v = *reinterpret_cast<const float4*>(&x[i]);
    float vs[4] = {v.x, v.y, v.z, v.w};
    __nv_bfloat162 hp[2], lp[2];
#pragma unroll
    for (int j = 0; j < 4; j++) {
        bf16 hh = __float2bfloat16(vs[j]);
        bf16 ll = __float2bfloat16(vs[j] - __bfloat162float(hh));
        if (j & 1) { hp[j >> 1].y = hh; lp[j >> 1].y = ll; }
        else       { hp[j >> 1].x = hh; lp[j >> 1].x = ll; }
    }
    *reinterpret_cast<__nv_bfloat162*>(&h[o])     = hp[0];
    *reinterpret_cast<__nv_bfloat162*>(&h[o + 2]) = hp[1];
    *reinterpret_cast<__nv_bfloat162*>(&l[o])     = lp[0];
    *reinterpret_cast<__nv_bfloat162*>(&l[o + 2]) = lp[1];
}

// ---------------- warp-MMA GEMM: Y[m][n] = sum_k X[m][k]*B[n][k] + bias ----
// 128x128 tile, BK=32, 8 warps (2m x 4n), warp tile 64x32, m16n8k16 bf16.
// Precision split: Y = Xh*Wh + Xh*Wl + Xl*Wh (fp32 accum).
// smem layout per tile: row stride 64B, 16B-chunk swizzle c' = c ^ ((row>>1)&3)
__global__ __launch_bounds__(256) void tgemm_kernel(
    const bf16* __restrict__ Xh_, const bf16* __restrict__ Xl_,
    const bf16* __restrict__ Wh_, const bf16* __restrict__ Wl_,
    const float* B0, const float* B1, const float* B2,
    float* Y0, float* Y1, float* Y2) {
    __shared__ __align__(1024) bf16 sAh[128 * 32];
    __shared__ __align__(1024) bf16 sAl[128 * 32];
    __shared__ __align__(1024) bf16 sBh[128 * 32];
    __shared__ __align__(1024) bf16 sBl[128 * 32];

    int z = blockIdx.z;
    const bf16* Xh = Xh_ + (size_t)z * NTOK * D_MODEL;
    const bf16* Xl = Xl_ + (size_t)z * NTOK * D_MODEL;
    const bf16* Wh = Wh_ + (size_t)z * D_MODEL * D_MODEL;
    const bf16* Wl = Wl_ + (size_t)z * D_MODEL * D_MODEL;
    const float* bias = (z == 0) ? B0 : (z == 1) ? B1 : B2;
    float* Y = (z == 0) ? Y0 : (z == 1) ? Y1 : Y2;

    int tid = threadIdx.x;
    int lane = tid & 31, wid = tid >> 5;
    int wm = wid >> 2, wn = wid & 3;
    int brow = blockIdx.y * 128;
    int bcol = blockIdx.x * 128;

    uint32_t aAh = smem_u32(sAh), aAl = smem_u32(sAl);
    uint32_t aBh = smem_u32(sBh), aBl = smem_u32(sBl);

    // global->smem mapping: row = tid>>1 (0..127), half = tid&1 (two 16B chunks)
    int row = tid >> 1, half = tid & 1;
    uint32_t swr = (uint32_t)((row >> 1) & 3);
    uint32_t so0 = (uint32_t)row * 64u + ((((uint32_t)half * 2u) ^ swr) << 4);
    uint32_t so1 = (uint32_t)row * 64u + ((((uint32_t)half * 2u + 1u) ^ swr) << 4);
    const bf16* gAh = Xh + (size_t)(brow + row) * D_MODEL + half * 16;
    const bf16* gAl = Xl + (size_t)(brow + row) * D_MODEL + half * 16;
    const bf16* gBh = Wh + (size_t)(bcol + row) * D_MODEL + half * 16;
    const bf16* gBl = Wl + (size_t)(bcol + row) * D_MODEL + half * 16;

    // ldmatrix lane addressing precompute
    int l15 = lane & 15;
    uint32_t csA = (uint32_t)(lane >> 4);        // A: 0 for k-lo matrices, 1 for k-hi
    uint32_t csB = (uint32_t)((lane >> 3) & 1);  // B: 0 lo, 1 hi
    uint32_t aRowA[4], swA[4];
#pragma unroll
    for (int mi = 0; mi < 4; mi++) {
        int r = wm * 64 + mi * 16 + l15;
        aRowA[mi] = (uint32_t)r * 64u;
        swA[mi] = (uint32_t)((r >> 1) & 3);
    }
    uint32_t aRowB[4], swB[4];
#pragma unroll
    for (int ni = 0; ni < 4; ni++) {
        int r = wn * 32 + ni * 8 + (lane & 7);
        aRowB[ni] = (uint32_t)r * 64u;
        swB[ni] = (uint32_t)((r >> 1) & 3);
    }

    float acc[4][4][4];
#pragma unroll
    for (int mi = 0; mi < 4; mi++)
#pragma unroll
        for (int ni = 0; ni < 4; ni++)
#pragma unroll
            for (int c = 0; c < 4; c++) acc[mi][ni][c] = 0.0f;

    for (int kc = 0; kc < D_MODEL / 32; kc++) {
        int k0 = kc * 32;
        __syncthreads();
        *reinterpret_cast<uint4*>(reinterpret_cast<char*>(sAh) + so0) =
            *reinterpret_cast<const uint4*>(gAh + k0);
        *reinterpret_cast<uint4*>(reinterpret_cast<char*>(sAh) + so1) =
            *reinterpret_cast<const uint4*>(gAh + k0 + 8);
        *reinterpret_cast<uint4*>(reinterpret_cast<char*>(sAl) + so0) =
            *reinterpret_cast<const uint4*>(gAl + k0);
        *reinterpret_cast<uint4*>(reinterpret_cast<char*>(sAl) + so1) =
            *reinterpret_cast<const uint4*>(gAl + k0 + 8);
        *reinterpret_cast<uint4*>(reinterpret_cast<char*>(sBh) + so0) =
            *reinterpret_cast<const uint4*>(gBh + k0);
        *reinterpret_cast<uint4*>(reinterpret_cast<char*>(sBh) + so1) =
            *reinterpret_cast<const uint4*>(gBh + k0 + 8);
        *reinterpret_cast<uint4*>(reinterpret_cast<char*>(sBl) + so0) =
            *reinterpret_cast<const uint4*>(gBl + k0);
        *reinterpret_cast<uint4*>(reinterpret_cast<char*>(sBl) + so1) =
            *reinterpret_cast<const uint4*>(gBl + k0 + 8);
        __syncthreads();

#pragma unroll
        for (int ks = 0; ks < 2; ks++) {
            uint32_t kchA = (uint32_t)ks * 2u + csA;
            uint32_t kchB = (uint32_t)ks * 2u + csB;
            uint32_t ah[4][4], bh[4][2], bl[4][2];
#pragma unroll
            for (int mi = 0; mi < 4; mi++)
                ldm_x4(ah[mi], aAh + aRowA[mi] + (((kchA ^ swA[mi])) << 4));
#pragma unroll
            for (int ni = 0; ni < 4; ni++) {
                ldm_x2(bh[ni], aBh + aRowB[ni] + (((kchB ^ swB[ni])) << 4));
                ldm_x2(bl[ni], aBl + aRowB[ni] + (((kchB ^ swB[ni])) << 4));
            }
#pragma unroll
            for (int mi = 0; mi < 4; mi++)
#pragma unroll
                for (int ni = 0; ni < 4; ni++) {
                    mma_bf16(acc[mi][ni], ah[mi], bh[ni]);
                    mma_bf16(acc[mi][ni], ah[mi], bl[ni]);
                }
            uint32_t al[4][4];
#pragma unroll
            for (int mi = 0; mi < 4; mi++)
                ldm_x4(al[mi], aAl + aRowA[mi] + (((kchA ^ swA[mi])) << 4));
#pragma unroll
            for (int mi = 0; mi < 4; mi++)
#pragma unroll
                for (int ni = 0; ni < 4; ni++)
                    mma_bf16(acc[mi][ni], al[mi], bh[ni]);
        }
    }

    // epilogue: fragment c0=C[g][2t], c1=C[g][2t+1], c2=C[g+8][2t], c3=C[g+8][2t+1]
    int g = lane >> 2, t = lane & 3;
#pragma unroll
    for (int ni = 0; ni < 4; ni++) {
        int gcol = bcol + wn * 32 + ni * 8 + 2 * t;
        float2 b2 = *reinterpret_cast<const float2*>(&bias[gcol]);
#pragma unroll
        for (int mi = 0; mi < 4; mi++) {
            int grow = brow + wm * 64 + mi * 16 + g;
            float2 o0 = make_float2(acc[mi][ni][0] + b2.x, acc[mi][ni][1] + b2.y);
            float2 o1 = make_float2(acc[mi][ni][2] + b2.x, acc[mi][ni][3] + b2.y);
            *reinterpret_cast<float2*>(&Y[(size_t)grow * D_MODEL + gcol]) = o0;
            *reinterpret_cast<float2*>(&Y[(size_t)(grow + 8) * D_MODEL + gcol]) = o1;
        }
    }
}

// ---------------- attention (round-5 best, unchanged) ----------------------
#define AST 68
#define ATT_SMEM (4 * 64 * AST * 4)
#define QSCALE (0.125f * 1.4426950408889634f)

__global__ __launch_bounds__(256, 2) void attn_kernel(
    const float* __restrict__ q, const float* __restrict__ k,
    const float* __restrict__ v, float* __restrict__ o) {
    extern __shared__ float sm[];
    float* Qs = sm;
    float* Ks = sm + 64 * AST;
    float* Vs = Ks + 64 * AST;
    float* Ss = Vs + 64 * AST;

    int qt = blockIdx.x;
    int bh = blockIdx.y;
    int b = bh / NHEAD;
    int h = bh - b * NHEAD;
    size_t base = (size_t)b * SEQ * D_MODEL + (size_t)h * 64;

    int tid = threadIdx.x;
    int lr = tid >> 2;
    int lc = (tid & 3) * 16;
    int sr = (tid >> 4) * 4;
    int tc = tid & 15;

    {
        const float* src = q + base + (size_t)(qt * 64 + lr) * D_MODEL + lc;
        float4* dst = reinterpret_cast<float4*>(&Qs[lr * AST + lc]);
#pragma unroll
        for (int i = 0; i < 4; i++) {
            float4 qv = reinterpret_cast<const float4*>(src)[i];
            qv.x *= QSCALE; qv.y *= QSCALE; qv.z *= QSCALE; qv.w *= QSCALE;
            dst[i] = qv;
        }
    }

    float m = -1e30f, l = 0.0f;
    ull oacc[8];
#pragma unroll
    for (int i = 0; i < 8; i++) oacc[i] = 0ULL;

    for (int kt0 = 0; kt0 < SEQ; kt0 += 64) {
        {
            const float* ksrc = k + base + (size_t)(kt0 + lr) * D_MODEL + lc;
            const float* vsrc = v + base + (size_t)(kt0 + lr) * D_MODEL + lc;
            float4* kdst = reinterpret_cast<float4*>(&Ks[lr * AST + lc]);
            float4* vdst = reinterpret_cast<float4*>(&Vs[lr * AST + lc]);
#pragma unroll
            for (int i = 0; i < 4; i++) {
                kdst[i] = reinterpret_cast<const float4*>(ksrc)[i];
                vdst[i] = reinterpret_cast<const float4*>(vsrc)[i];
            }
        }
        __syncthreads();

        {
            ull sacc[4][4];
#pragma unroll
            for (int i = 0; i < 4; i++)
#pragma unroll
                for (int g = 0; g < 4; g++) sacc[i][g] = 0ULL;
#pragma unroll 2
            for (int d0 = 0; d0 < 64; d0 += 4) {
                ulonglong2 qp[4], kp[4];
#pragma unroll
                for (int i = 0; i < 4; i++)
                    qp[i] = *reinterpret_cast<const ulonglong2*>(&Qs[(sr + i) * AST + d0]);
#pragma unroll
                for (int g = 0; g < 4; g++)
                    kp[g] = *reinterpret_cast<const ulonglong2*>(&Ks[(tc + 16 * g) * AST + d0]);
#pragma unroll
                for (int i = 0; i < 4; i++)
#pragma unroll
                    for (int g = 0; g < 4; g++) {
                        fma2(sacc[i][g], qp[i].x, kp[g].x);
                        fma2(sacc[i][g], qp[i].y, kp[g].y);
                    }
            }
#pragma unroll
            for (int i = 0; i < 4; i++)
#pragma unroll
                for (int g = 0; g < 4; g++) {
                    float2 t = upk2(sacc[i][g]);
                    Ss[(sr + i) * AST + tc + 16 * g] = t.x + t.y;
                }
        }
        __syncthreads();

        {
            float* srow = &Ss[lr * AST + lc];
            float s[16];
#pragma unroll
            for (int i = 0; i < 4; i++) {
                float4 sv = *reinterpret_cast<const float4*>(&srow[4 * i]);
                s[4 * i] = sv.x; s[4 * i + 1] = sv.y;
                s[4 * i + 2] = sv.z; s[4 * i + 3] = sv.w;
            }
            float rmax = s[0];
#pragma unroll
            for (int i = 1; i < 16; i++) rmax = fmaxf(rmax, s[i]);
            rmax = fmaxf(rmax, __shfl_xor_sync(0xffffffffu, rmax, 1));
            rmax = fmaxf(rmax, __shfl_xor_sync(0xffffffffu, rmax, 2));
            float newm = fmaxf(m, rmax);
            float alpha = fexp2(m - newm);
            m = newm;
            float rsum = 0.0f;
#pragma unroll
            for (int i = 0; i < 16; i++) {
                s[i] = fexp2(s[i] - newm);
                rsum += s[i];
            }
            rsum += __shfl_xor_sync(0xffffffffu, rsum, 1);
            rsum += __shfl_xor_sync(0xffffffffu, rsum, 2);
            l = l * alpha + rsum;
#pragma unroll
            for (int i = 0; i < 4; i++) {
                float4 pv = make_float4(s[4 * i], s[4 * i + 1], s[4 * i + 2], s[4 * i + 3]);
                *reinterpret_cast<float4*>(&srow[4 * i]) = pv;
            }
            ull ad = pk2(alpha, alpha);
#pragma unroll
            for (int i = 0; i < 8; i++) mul2(oacc[i], oacc[i], ad);
        }
        __syncwarp();

        {
            const float* prow = &Ss[lr * AST];
#pragma unroll 4
            for (int j = 0; j < 64; j++) {
                float pj = prow[j];
                ull pd = pk2(pj, pj);
                const ulonglong2* vp =
                    reinterpret_cast<const ulonglong2*>(&Vs[j * AST + lc]);
                ulonglong2 v0 = vp[0];
                ulonglong2 v1 = vp[1];
                fma2(oacc[0], pd, v0.x);
                fma2(oacc[1], pd, v0.y);
                fma2(oacc[2], pd, v1.x);
                fma2(oacc[3], pd, v1.y);
                ulonglong2 v2 = vp[2];
                ulonglong2 v3 = vp[3];
                fma2(oacc[4], pd, v2.x);
                fma2(oacc[5], pd, v2.y);
                fma2(oacc[6], pd, v3.x);
                fma2(oacc[7], pd, v3.y);
            }
        }
        __syncthreads();
    }

    float inv = 1.0f / l;
    float* dst = o + base + (size_t)(qt * 64 + lr) * D_MODEL + lc;
#pragma unroll
    for (int i = 0; i < 4; i++) {
        float2 p0 = upk2(oacc[2 * i + 0]);
        float2 p1 = upk2(oacc[2 * i + 1]);
        float4 ov = make_float4(p0.x * inv, p0.y * inv, p1.x * inv, p1.y * inv);
        reinterpret_cast<float4*>(dst)[i] = ov;
    }
}

// ---------------- launch ---------------------------------------------------
extern "C" void kernel_launch(void* const* d_in, const int* in_sizes, int n_in,
                              void* d_out, int out_size) {
    const float* query = (const float*)d_in[0];
    const float* key_  = (const float*)d_in[1];
    const float* value = (const float*)d_in[2];
    const float* Wq = (const float*)d_in[3];
    const float* bq = (const float*)d_in[4];
    const float* Aq = (const float*)d_in[5];
    const float* Wk = (const float*)d_in[6];
    const float* bk = (const float*)d_in[7];
    const float* Ak = (const float*)d_in[8];
    const float* Wv = (const float*)d_in[9];
    const float* bv = (const float*)d_in[10];
    const float* Av = (const float*)d_in[11];
    const float* Wo = (const float*)d_in[12];
    const float* bo = (const float*)d_in[13];
    float* out = (float*)d_out;

    bf16 *pwh, *pwl, *pxh, *pxl;
    float *pq, *pk, *pv, *pao;
    cudaGetSymbolAddress((void**)&pwh, g_wh);
    cudaGetSymbolAddress((void**)&pwl, g_wl);
    cudaGetSymbolAddress((void**)&pxh, g_xh);
    cudaGetSymbolAddress((void**)&pxl, g_xl);
    cudaGetSymbolAddress((void**)&pq, g_q);
    cudaGetSymbolAddress((void**)&pk, g_k);
    cudaGetSymbolAddress((void**)&pv, g_v);
    cudaGetSymbolAddress((void**)&pao, g_ao);

    cudaFuncSetAttribute(attn_kernel,
                         cudaFuncAttributeMaxDynamicSharedMemorySize, ATT_SMEM);

    // #0: weight build + bf16 split
    int nw = D_MODEL * D_MODEL;
    dim3 wgrid((nw + 255) / 256, 4);
    wsplit_kernel<<<wgrid, 256>>>(Wq, Aq, Wk, Ak, Wv, Av, Wo, pwh, pwl);

    // #1: split q/k/v inputs to bf16 hi/lo
    int nx = NTOK * D_MODEL / 4;
    dim3 xgrid((nx + 255) / 256, 1, 3);
    xsplit_kernel<<<xgrid, 256>>>(query, key_, value, pxh, pxl);

    // #2: qkv projections on tensor cores (warp mma)
    dim3 ggrid(D_MODEL / 128, NTOK / 128, 3);
    tgemm_kernel<<<ggrid, 256>>>(pxh, pxl, pwh, pwl, bq, bk, bv, pq, pk, pv);

    // #3: attention (profiled slot)
    dim3 agrid(SEQ / 64, 2 * NHEAD);
    attn_kernel<<<agrid, 256, ATT_SMEM>>>(pq, pk, pv, pao);

    // #4: split attention output
    dim3 x1grid((nx + 255) / 256, 1, 1);
    xsplit_kernel<<<x1grid, 256>>>(pao, pao, pao, pxh, pxl);

    // #5: output projection (weight slot 3)
    dim3 ogrid(D_MODEL / 128, NTOK / 128, 1);
    tgemm_kernel<<<ogrid, 256>>>(pxh, pxl,
                                 pwh + 3 * (size_t)nw, pwl + 3 * (size_t)nw,
                                 bo, bo, bo, out, out, out);
}

// round 9
// speedup vs baseline: 4.7340x; 4.1419x over previous
#include <cuda_runtime.h>
#include <cuda_bf16.h>
#include <cstdint>

#define D_MODEL 768
#define NTOK 4096           // B*S = 2*2048
#define SEQ 2048
#define NHEAD 12
#define LORA_R 16
#define LORA_SCALE 4.0f
#define QSCALE (0.125f * 1.4426950408889634f)   // 1/sqrt(64) * log2(e)

typedef unsigned long long ull;
typedef __nv_bfloat16 bf16;

// ---------------- helpers ---------------------------------------------------
__device__ __forceinline__ float fexp2(float x) {
    float r;
    asm("ex2.approx.ftz.f32 %0, %1;" : "=f"(r) : "f"(x));
    return r;
}
__device__ __forceinline__ uint32_t smem_u32(const void* p) {
    uint32_t a;
    asm("{ .reg .u64 t; cvta.to.shared.u64 t, %1; cvt.u32.u64 %0, t; }"
        : "=r"(a) : "l"(p));
    return a;
}
// pack truncated-bf16 of two floats: lo half = hi16(a), hi half = hi16(b)
__device__ __forceinline__ uint32_t prmt_hi(float a, float b) {
    uint32_t r;
    asm("prmt.b32 %0, %1, %2, 0x7632;" : "=r"(r)
        : "r"(__float_as_uint(a)), "r"(__float_as_uint(b)));
    return r;
}
__device__ __forceinline__ float truncbf(float a) {
    return __uint_as_float(__float_as_uint(a) & 0xFFFF0000u);
}
// bf16x2 with lo = round(lo), hi = round(hi)
__device__ __forceinline__ uint32_t cvt2bf(float lo, float hi) {
    uint32_t r;
    asm("cvt.rn.bf16x2.f32 %0, %1, %2;" : "=r"(r) : "f"(hi), "f"(lo));
    return r;
}

// ---------------- warp MMA primitives (baseline PTX) -----------------------
__device__ __forceinline__ void ldm_x4(uint32_t* f, uint32_t addr) {
    asm volatile("ldmatrix.sync.aligned.m8n8.x4.shared.b16 {%0,%1,%2,%3}, [%4];"
                 : "=r"(f[0]), "=r"(f[1]), "=r"(f[2]), "=r"(f[3]) : "r"(addr));
}
__device__ __forceinline__ void ldm_x2(uint32_t* f, uint32_t addr) {
    asm volatile("ldmatrix.sync.aligned.m8n8.x2.shared.b16 {%0,%1}, [%2];"
                 : "=r"(f[0]), "=r"(f[1]) : "r"(addr));
}
__device__ __forceinline__ void ldm_x2t(uint32_t* f, uint32_t addr) {
    asm volatile("ldmatrix.sync.aligned.m8n8.x2.trans.shared.b16 {%0,%1}, [%2];"
                 : "=r"(f[0]), "=r"(f[1]) : "r"(addr));
}
__device__ __forceinline__ void mma_bf16(float* c, const uint32_t* a, const uint32_t* b) {
    asm volatile(
        "mma.sync.aligned.m16n8k16.row.col.f32.bf16.bf16.f32 "
        "{%0,%1,%2,%3}, {%4,%5,%6,%7}, {%8,%9}, {%0,%1,%2,%3};"
        : "+f"(c[0]), "+f"(c[1]), "+f"(c[2]), "+f"(c[3])
        : "r"(a[0]), "r"(a[1]), "r"(a[2]), "r"(a[3]), "r"(b[0]), "r"(b[1]));
}

// ---------------- scratch ---------------------------------------------------
__device__ bf16 g_wh[4 * D_MODEL * D_MODEL];
__device__ bf16 g_wl[4 * D_MODEL * D_MODEL];
__device__ bf16 g_xh[3 * NTOK * D_MODEL];   // input splits; slot0 reused for O splits
__device__ bf16 g_xl[3 * NTOK * D_MODEL];
__device__ bf16 g_yh[3 * NTOK * D_MODEL];   // q/k/v splits (q pre-scaled by QSCALE)
__device__ bf16 g_yl[3 * NTOK * D_MODEL];

// ---------------- weight build + bf16 split: B[n][k] = W[n][k] + s<A_n,A_k> -
__global__ void wsplit_kernel(const float* __restrict__ Wq, const float* __restrict__ Aq,
                              const float* __restrict__ Wk, const float* __restrict__ Ak,
                              const float* __restrict__ Wv, const float* __restrict__ Av,
                              const float* __restrict__ Wo,
                              bf16* __restrict__ wh, bf16* __restrict__ wl) {
    int which = blockIdx.y;
    const float* W = (which == 0) ? Wq : (which == 1) ? Wk : (which == 2) ? Wv : Wo;
    const float* A = (which == 0) ? Aq : (which == 1) ? Ak : Av;
    int idx = blockIdx.x * blockDim.x + threadIdx.x;
    if (idx >= D_MODEL * D_MODEL) return;
    int n = idx / D_MODEL;
    int k = idx - n * D_MODEL;
    float acc = W[idx];
    if (which < 3) {
        float s = 0.0f;
#pragma unroll
        for (int r = 0; r < LORA_R; r++)
            s += A[n * LORA_R + r] * A[k * LORA_R + r];
        acc += LORA_SCALE * s;
    }
    bf16 h = __float2bfloat16(acc);
    bf16 l = __float2bfloat16(acc - __bfloat162float(h));
    size_t o = (size_t)which * D_MODEL * D_MODEL + idx;
    wh[o] = h;
    wl[o] = l;
}

// ---------------- activation bf16 split (inputs) ---------------------------
__global__ void xsplit_kernel(const float* __restrict__ x0,
                              const float* __restrict__ x1,
                              const float* __restrict__ x2,
                              bf16* __restrict__ h, bf16* __restrict__ l) {
    int z = blockIdx.z;
    const float* x = (z == 0) ? x0 : (z == 1) ? x1 : x2;
    size_t i = ((size_t)blockIdx.x * blockDim.x + threadIdx.x) * 4;
    if (i >= (size_t)NTOK * D_MODEL) return;
    size_t o = (size_t)z * NTOK * D_MODEL + i;
    float4 v = *reinterpret_cast<const float4*>(&x[i]);
    *reinterpret_cast<uint32_t*>(&h[o])     = prmt_hi(v.x, v.y);
    *reinterpret_cast<uint32_t*>(&h[o + 2]) = prmt_hi(v.z, v.w);
    *reinterpret_cast<uint32_t*>(&l[o])     = cvt2bf(v.x - truncbf(v.x), v.y - truncbf(v.y));
    *reinterpret_cast<uint32_t*>(&l[o + 2]) = cvt2bf(v.z - truncbf(v.z), v.w - truncbf(v.w));
}

// ---------------- warp-MMA GEMM with split-producing epilogue --------------
// 128x128 tile, BK=32, 8 warps (2m x 4n), m16n8k16 bf16, 3-term split.
__global__ __launch_bounds__(256) void tgemm_kernel(
    const bf16* __restrict__ Xh_, const bf16* __restrict__ Xl_,
    const bf16* __restrict__ Wh_, const bf16* __restrict__ Wl_,
    const float* B0, const float* B1, const float* B2,
    float* __restrict__ Yf,            // fp32 output (or null)
    bf16* __restrict__ Yh_, bf16* __restrict__ Yl_,  // split output bases (or null)
    float qscale) {
    __shared__ __align__(1024) bf16 sAh[128 * 32];
    __shared__ __align__(1024) bf16 sAl[128 * 32];
    __shared__ __align__(1024) bf16 sBh[128 * 32];
    __shared__ __align__(1024) bf16 sBl[128 * 32];

    int z = blockIdx.z;
    const bf16* Xh = Xh_ + (size_t)z * NTOK * D_MODEL;
    const bf16* Xl = Xl_ + (size_t)z * NTOK * D_MODEL;
    const bf16* Wh = Wh_ + (size_t)z * D_MODEL * D_MODEL;
    const bf16* Wl = Wl_ + (size_t)z * D_MODEL * D_MODEL;
    const float* bias = (z == 0) ? B0 : (z == 1) ? B1 : B2;
    float ss = (z == 0) ? qscale : 1.0f;

    int tid = threadIdx.x;
    int lane = tid & 31, wid = tid >> 5;
    int wm = wid >> 2, wn = wid & 3;
    int brow = blockIdx.y * 128;
    int bcol = blockIdx.x * 128;

    uint32_t aAh = smem_u32(sAh), aAl = smem_u32(sAl);
    uint32_t aBh = smem_u32(sBh), aBl = smem_u32(sBl);

    int row = tid >> 1, half = tid & 1;
    uint32_t swr = (uint32_t)((row >> 1) & 3);
    uint32_t so0 = (uint32_t)row * 64u + ((((uint32_t)half * 2u) ^ swr) << 4);
    uint32_t so1 = (uint32_t)row * 64u + ((((uint32_t)half * 2u + 1u) ^ swr) << 4);
    const bf16* gAh = Xh + (size_t)(brow + row) * D_MODEL + half * 16;
    const bf16* gAl = Xl + (size_t)(brow + row) * D_MODEL + half * 16;
    const bf16* gBh = Wh + (size_t)(bcol + row) * D_MODEL + half * 16;
    const bf16* gBl = Wl + (size_t)(bcol + row) * D_MODEL + half * 16;

    int l15 = lane & 15;
    uint32_t csA = (uint32_t)(lane >> 4);
    uint32_t csB = (uint32_t)((lane >> 3) & 1);
    uint32_t aRowA[4], swA[4];
#pragma unroll
    for (int mi = 0; mi < 4; mi++) {
        int r = wm * 64 + mi * 16 + l15;
        aRowA[mi] = (uint32_t)r * 64u;
        swA[mi] = (uint32_t)((r >> 1) & 3);
    }
    uint32_t aRowB[4], swB[4];
#pragma unroll
    for (int ni = 0; ni < 4; ni++) {
        int r = wn * 32 + ni * 8 + (lane & 7);
        aRowB[ni] = (uint32_t)r * 64u;
        swB[ni] = (uint32_t)((r >> 1) & 3);
    }

    float acc[4][4][4];
#pragma unroll
    for (int mi = 0; mi < 4; mi++)
#pragma unroll
        for (int ni = 0; ni < 4; ni++)
#pragma unroll
            for (int c = 0; c < 4; c++) acc[mi][ni][c] = 0.0f;

    for (int kc = 0; kc < D_MODEL / 32; kc++) {
        int k0 = kc * 32;
        __syncthreads();
        *reinterpret_cast<uint4*>(reinterpret_cast<char*>(sAh) + so0) =
            *reinterpret_cast<const uint4*>(gAh + k0);
        *reinterpret_cast<uint4*>(reinterpret_cast<char*>(sAh) + so1) =
            *reinterpret_cast<const uint4*>(gAh + k0 + 8);
        *reinterpret_cast<uint4*>(reinterpret_cast<char*>(sAl) + so0) =
            *reinterpret_cast<const uint4*>(gAl + k0);
        *reinterpret_cast<uint4*>(reinterpret_cast<char*>(sAl) + so1) =
            *reinterpret_cast<const uint4*>(gAl + k0 + 8);
        *reinterpret_cast<uint4*>(reinterpret_cast<char*>(sBh) + so0) =
            *reinterpret_cast<const uint4*>(gBh + k0);
        *reinterpret_cast<uint4*>(reinterpret_cast<char*>(sBh) + so1) =
            *reinterpret_cast<const uint4*>(gBh + k0 + 8);
        *reinterpret_cast<uint4*>(reinterpret_cast<char*>(sBl) + so0) =
            *reinterpret_cast<const uint4*>(gBl + k0);
        *reinterpret_cast<uint4*>(reinterpret_cast<char*>(sBl) + so1) =
            *reinterpret_cast<const uint4*>(gBl + k0 + 8);
        __syncthreads();

#pragma unroll
        for (int ks = 0; ks < 2; ks++) {
            uint32_t kchA = (uint32_t)ks * 2u + csA;
            uint32_t kchB = (uint32_t)ks * 2u + csB;
            uint32_t ah[4][4], bh[4][2], bl[4][2];
#pragma unroll
            for (int mi = 0; mi < 4; mi++)
                ldm_x4(ah[mi], aAh + aRowA[mi] + (((kchA ^ swA[mi])) << 4));
#pragma unroll
            for (int ni = 0; ni < 4; ni++) {
                ldm_x2(bh[ni], aBh + aRowB[ni] + (((kchB ^ swB[ni])) << 4));
                ldm_x2(bl[ni], aBl + aRowB[ni] + (((kchB ^ swB[ni])) << 4));
            }
#pragma unroll
            for (int mi = 0; mi < 4; mi++)
#pragma unroll
                for (int ni = 0; ni < 4; ni++) {
                    mma_bf16(acc[mi][ni], ah[mi], bh[ni]);
                    mma_bf16(acc[mi][ni], ah[mi], bl[ni]);
                }
            uint32_t al[4][4];
#pragma unroll
            for (int mi = 0; mi < 4; mi++)
                ldm_x4(al[mi], aAl + aRowA[mi] + (((kchA ^ swA[mi])) << 4));
#pragma unroll
            for (int mi = 0; mi < 4; mi++)
#pragma unroll
                for (int ni = 0; ni < 4; ni++)
                    mma_bf16(acc[mi][ni], al[mi], bh[ni]);
        }
    }

    bf16* Yh = Yh_ ? Yh_ + (size_t)z * NTOK * D_MODEL : nullptr;
    bf16* Yl = Yl_ ? Yl_ + (size_t)z * NTOK * D_MODEL : nullptr;

    int g = lane >> 2, t = lane & 3;
#pragma unroll
    for (int ni = 0; ni < 4; ni++) {
        int gcol = bcol + wn * 32 + ni * 8 + 2 * t;
        float2 b2 = *reinterpret_cast<const float2*>(&bias[gcol]);
#pragma unroll
        for (int mi = 0; mi < 4; mi++) {
            size_t grow = brow + wm * 64 + mi * 16 + g;
            float y0 = acc[mi][ni][0] + b2.x, y1 = acc[mi][ni][1] + b2.y;
            float y2 = acc[mi][ni][2] + b2.x, y3 = acc[mi][ni][3] + b2.y;
            if (Yf) {
                *reinterpret_cast<float2*>(&Yf[grow * D_MODEL + gcol]) =
                    make_float2(y0, y1);
                *reinterpret_cast<float2*>(&Yf[(grow + 8) * D_MODEL + gcol]) =
                    make_float2(y2, y3);
            }
            if (Yh) {
                float s0 = y0 * ss, s1 = y1 * ss, s2 = y2 * ss, s3 = y3 * ss;
                *reinterpret_cast<uint32_t*>(&Yh[grow * D_MODEL + gcol]) =
                    prmt_hi(s0, s1);
                *reinterpret_cast<uint32_t*>(&Yl[grow * D_MODEL + gcol]) =
                    cvt2bf(s0 - truncbf(s0), s1 - truncbf(s1));
                *reinterpret_cast<uint32_t*>(&Yh[(grow + 8) * D_MODEL + gcol]) =
                    prmt_hi(s2, s3);
                *reinterpret_cast<uint32_t*>(&Yl[(grow + 8) * D_MODEL + gcol]) =
                    cvt2bf(s2 - truncbf(s2), s3 - truncbf(s3));
            }
        }
    }
}

// ---------------- attention: tensor-core flash, 128q x 64k tiles -----------
// 8 warps x 16 query rows; S/P fragments entirely in registers; K/V via
// ldmatrix from swizzled smem (chunk' = chunk ^ (row&7), row stride 128B).
__global__ __launch_bounds__(256, 2) void attn_kernel(
    const bf16* __restrict__ qh_, const bf16* __restrict__ ql_,
    const bf16* __restrict__ kh_, const bf16* __restrict__ kl_,
    const bf16* __restrict__ vh_, const bf16* __restrict__ vl_,
    bf16* __restrict__ oh_, bf16* __restrict__ ol_) {
    __shared__ __align__(1024) char smem[32768];
    uint32_t sb = smem_u32(smem);

    int tid = threadIdx.x;
    int lane = tid & 31, wid = tid >> 5;       // 8 warps
    int qt = blockIdx.x;                        // 16 q-tiles of 128
    int bh = blockIdx.y;                        // 24
    int b = bh / NHEAD, h = bh - b * NHEAD;
    size_t base = (size_t)b * SEQ * D_MODEL + (size_t)h * 64;

    // ---- stage Q (hi at 0, lo at 16K) and load Q fragments once ----
#pragma unroll
    for (int i = 0; i < 8; i++) {
        int idx = tid + 256 * i;                // 0..2047
        const bf16* src = (idx < 1024) ? qh_ : ql_;
        int li = idx & 1023;
        int r = li >> 3, c = li & 7;
        uint4 v = *reinterpret_cast<const uint4*>(
            src + base + (size_t)(qt * 128 + r) * D_MODEL + c * 8);
        *reinterpret_cast<uint4*>(smem + ((idx < 1024) ? 0 : 16384) +
                                  r * 128 + (((c ^ (r & 7))) << 4)) = v;
    }
    __syncthreads();

    uint32_t fqh[4][4], fql[4][4];
    {
        int l15 = lane & 15, lhi = lane >> 4;
        int r = wid * 16 + l15;
#pragma unroll
        for (int kk = 0; kk < 4; kk++) {
            uint32_t ad = sb + r * 128 + ((((2 * kk + lhi) ^ (r & 7))) << 4);
            ldm_x4(fqh[kk], ad);
            ldm_x4(fql[kk], ad + 16384);
        }
    }
    __syncthreads();

    float m0 = -1e30f, m1 = -1e30f, l0 = 0.0f, l1 = 0.0f;
    float o[8][4];
#pragma unroll
    for (int j = 0; j < 8; j++)
#pragma unroll
        for (int c = 0; c < 4; c++) o[j][c] = 0.0f;

    int bl8 = lane & 7, bsel = (lane >> 3) & 1;

    for (int kt = 0; kt < SEQ; kt += 64) {
        // load K/V tiles: Kh@0, Kl@8K, Vh@16K, Vl@24K
#pragma unroll
        for (int i = 0; i < 8; i++) {
            int idx = tid + 256 * i;            // 0..2047
            int tsel = idx >> 9;                // 0..3
            int li = idx & 511;
            int r = li >> 3, c = li & 7;
            const bf16* src = (tsel == 0) ? kh_ : (tsel == 1) ? kl_
                            : (tsel == 2) ? vh_ : vl_;
            uint4 v = *reinterpret_cast<const uint4*>(
                src + base + (size_t)(kt + r) * D_MODEL + c * 8);
            *reinterpret_cast<uint4*>(smem + tsel * 8192 +
                                      r * 128 + (((c ^ (r & 7))) << 4)) = v;
        }
        __syncthreads();

        // S = Q K^T  (per warp: 16 rows x 64 keys, 8 n-tiles)
        float s[8][4];
#pragma unroll
        for (int j = 0; j < 8; j++)
#pragma unroll
            for (int c = 0; c < 4; c++) s[j][c] = 0.0f;
#pragma unroll
        for (int kk = 0; kk < 4; kk++) {
#pragma unroll
            for (int j = 0; j < 8; j++) {
                int br = 8 * j + bl8;
                uint32_t ad = sb + br * 128 + ((((2 * kk + bsel) ^ (br & 7))) << 4);
                uint32_t khf[2], klf[2];
                ldm_x2(khf, ad);
                mma_bf16(s[j], fqh[kk], khf);
                mma_bf16(s[j], fql[kk], khf);
                ldm_x2(klf, ad + 8192);
                mma_bf16(s[j], fqh[kk], klf);
            }
        }

        // online softmax over the 64 keys (rows g and g+8 per thread)
        float rmax0 = s[0][0], rmax1 = s[0][2];
#pragma unroll
        for (int j = 0; j < 8; j++) {
            rmax0 = fmaxf(rmax0, fmaxf(s[j][0], s[j][1]));
            rmax1 = fmaxf(rmax1, fmaxf(s[j][2], s[j][3]));
        }
        rmax0 = fmaxf(rmax0, __shfl_xor_sync(0xffffffffu, rmax0, 1));
        rmax0 = fmaxf(rmax0, __shfl_xor_sync(0xffffffffu, rmax0, 2));
        rmax1 = fmaxf(rmax1, __shfl_xor_sync(0xffffffffu, rmax1, 1));
        rmax1 = fmaxf(rmax1, __shfl_xor_sync(0xffffffffu, rmax1, 2));
        float nm0 = fmaxf(m0, rmax0), nm1 = fmaxf(m1, rmax1);
        float a0 = fexp2(m0 - nm0), a1 = fexp2(m1 - nm1);
        m0 = nm0; m1 = nm1;
        float rs0 = 0.0f, rs1 = 0.0f;
#pragma unroll
        for (int j = 0; j < 8; j++) {
            s[j][0] = fexp2(s[j][0] - nm0);
            s[j][1] = fexp2(s[j][1] - nm0);
            s[j][2] = fexp2(s[j][2] - nm1);
            s[j][3] = fexp2(s[j][3] - nm1);
            rs0 += s[j][0] + s[j][1];
            rs1 += s[j][2] + s[j][3];
        }
        rs0 += __shfl_xor_sync(0xffffffffu, rs0, 1);
        rs0 += __shfl_xor_sync(0xffffffffu, rs0, 2);
        rs1 += __shfl_xor_sync(0xffffffffu, rs1, 1);
        rs1 += __shfl_xor_sync(0xffffffffu, rs1, 2);
        l0 = l0 * a0 + rs0;
        l1 = l1 * a1 + rs1;
#pragma unroll
        for (int j = 0; j < 8; j++) {
            o[j][0] *= a0; o[j][1] *= a0;
            o[j][2] *= a1; o[j][3] *= a1;
        }

        // PV: pack P fragments per k-step from S fragments, mma against V^T
#pragma unroll
        for (int kk = 0; kk < 4; kk++) {
            int j0 = 2 * kk, j1 = 2 * kk + 1;
            uint32_t ph[4], pl[4];
            ph[0] = prmt_hi(s[j0][0], s[j0][1]);
            ph[1] = prmt_hi(s[j0][2], s[j0][3]);
            ph[2] = prmt_hi(s[j1][0], s[j1][1]);
            ph[3] = prmt_hi(s[j1][2], s[j1][3]);
            pl[0] = cvt2bf(s[j0][0] - truncbf(s[j0][0]), s[j0][1] - truncbf(s[j0][1]));
            pl[1] = cvt2bf(s[j0][2] - truncbf(s[j0][2]), s[j0][3] - truncbf(s[j0][3]));
            pl[2] = cvt2bf(s[j1][0] - truncbf(s[j1][0]), s[j1][1] - truncbf(s[j1][1]));
            pl[3] = cvt2bf(s[j1][2] - truncbf(s[j1][2]), s[j1][3] - truncbf(s[j1][3]));
            int vr = 16 * kk + bl8 + 8 * bsel;
#pragma unroll
            for (int j = 0; j < 8; j++) {
                uint32_t ad = sb + 16384 + vr * 128 + (((j ^ (vr & 7))) << 4);
                uint32_t vhf[2], vlf[2];
                ldm_x2t(vhf, ad);
                mma_bf16(o[j], ph, vhf);
                mma_bf16(o[j], pl, vhf);
                ldm_x2t(vlf, ad + 8192);
                mma_bf16(o[j], ph, vlf);
            }
        }
        __syncthreads();
    }

    // epilogue: O / l, write bf16 hi/lo splits
    float il0 = 1.0f / l0, il1 = 1.0f / l1;
    int g = lane >> 2, t2 = (lane & 3) * 2;
    size_t tok0 = (size_t)b * SEQ + qt * 128 + wid * 16 + g;
    size_t tok1 = tok0 + 8;
    int colbase = h * 64 + t2;
#pragma unroll
    for (int j = 0; j < 8; j++) {
        int col = colbase + 8 * j;
        float x0 = o[j][0] * il0, x1 = o[j][1] * il0;
        float x2 = o[j][2] * il1, x3 = o[j][3] * il1;
        *reinterpret_cast<uint32_t*>(&oh_[tok0 * D_MODEL + col]) = prmt_hi(x0, x1);
        *reinterpret_cast<uint32_t*>(&ol_[tok0 * D_MODEL + col]) =
            cvt2bf(x0 - truncbf(x0), x1 - truncbf(x1));
        *reinterpret_cast<uint32_t*>(&oh_[tok1 * D_MODEL + col]) = prmt_hi(x2, x3);
        *reinterpret_cast<uint32_t*>(&ol_[tok1 * D_MODEL + col]) =
            cvt2bf(x2 - truncbf(x2), x3 - truncbf(x3));
    }
}

// ---------------- launch ---------------------------------------------------
extern "C" void kernel_launch(void* const* d_in, const int* in_sizes, int n_in,
                              void* d_out, int out_size) {
    const float* query = (const float*)d_in[0];
    const float* key_  = (const float*)d_in[1];
    const float* value = (const float*)d_in[2];
    const float* Wq = (const float*)d_in[3];
    const float* bq = (const float*)d_in[4];
    const float* Aq = (const float*)d_in[5];
    const float* Wk = (const float*)d_in[6];
    const float* bk = (const float*)d_in[7];
    const float* Ak = (const float*)d_in[8];
    const float* Wv = (const float*)d_in[9];
    const float* bv = (const float*)d_in[10];
    const float* Av = (const float*)d_in[11];
    const float* Wo = (const float*)d_in[12];
    const float* bo = (const float*)d_in[13];
    float* out = (float*)d_out;

    bf16 *pwh, *pwl, *pxh, *pxl, *pyh, *pyl;
    cudaGetSymbolAddress((void**)&pwh, g_wh);
    cudaGetSymbolAddress((void**)&pwl, g_wl);
    cudaGetSymbolAddress((void**)&pxh, g_xh);
    cudaGetSymbolAddress((void**)&pxl, g_xl);
    cudaGetSymbolAddress((void**)&pyh, g_yh);
    cudaGetSymbolAddress((void**)&pyl, g_yl);

    size_t nw = D_MODEL * D_MODEL;
    size_t ntd = (size_t)NTOK * D_MODEL;

    // #0: weight build + bf16 split
    dim3 wgrid((int)((nw + 255) / 256), 4);
    wsplit_kernel<<<wgrid, 256>>>(Wq, Aq, Wk, Ak, Wv, Av, Wo, pwh, pwl);

    // #1: split q/k/v inputs
    int nx = NTOK * D_MODEL / 4;
    dim3 xgrid((nx + 255) / 256, 1, 3);
    xsplit_kernel<<<xgrid, 256>>>(query, key_, value, pxh, pxl);

    // #2: qkv projections -> bf16 splits directly (q scaled by QSCALE)
    dim3 ggrid(D_MODEL / 128, NTOK / 128, 3);
    tgemm_kernel<<<ggrid, 256>>>(pxh, pxl, pwh, pwl, bq, bk, bv,
                                 nullptr, pyh, pyl, QSCALE);

    // #3: attention (tensor-core flash) -> O splits (profiled slot)
    dim3 agrid(SEQ / 128, 2 * NHEAD);
    attn_kernel<<<agrid, 256>>>(pyh, pyl,
                                pyh + ntd, pyl + ntd,
                                pyh + 2 * ntd, pyl + 2 * ntd,
                                pxh, pxl);

    // #4: output projection (weight slot 3) -> fp32 out
    dim3 ogrid(D_MODEL / 128, NTOK / 128, 1);
    tgemm_kernel<<<ogrid, 256>>>(pxh, pxl, pwh + 3 * nw, pwl + 3 * nw,
                                 bo, bo, bo, out, nullptr, nullptr, 1.0f);
}

// round 10
// speedup vs baseline: 5.2619x; 1.1115x over previous
#include <cuda_runtime.h>
#include <cuda_bf16.h>
#include <cstdint>

#define D_MODEL 768
#define NTOK 4096           // B*S = 2*2048
#define SEQ 2048
#define NHEAD 12
#define LORA_R 16
#define LORA_SCALE 4.0f
#define QSCALE (0.125f * 1.4426950408889634f)   // 1/sqrt(64) * log2(e)

typedef unsigned long long ull;
typedef __nv_bfloat16 bf16;

// ---------------- helpers ---------------------------------------------------
__device__ __forceinline__ float fexp2(float x) {
    float r;
    asm("ex2.approx.ftz.f32 %0, %1;" : "=f"(r) : "f"(x));
    return r;
}
__device__ __forceinline__ uint32_t smem_u32(const void* p) {
    uint32_t a;
    asm("{ .reg .u64 t; cvta.to.shared.u64 t, %1; cvt.u32.u64 %0, t; }"
        : "=r"(a) : "l"(p));
    return a;
}
__device__ __forceinline__ uint32_t prmt_hi(float a, float b) {
    uint32_t r;
    asm("prmt.b32 %0, %1, %2, 0x7632;" : "=r"(r)
        : "r"(__float_as_uint(a)), "r"(__float_as_uint(b)));
    return r;
}
__device__ __forceinline__ float truncbf(float a) {
    return __uint_as_float(__float_as_uint(a) & 0xFFFF0000u);
}
__device__ __forceinline__ uint32_t cvt2bf(float lo, float hi) {
    uint32_t r;
    asm("cvt.rn.bf16x2.f32 %0, %1, %2;" : "=r"(r) : "f"(hi), "f"(lo));
    return r;
}
// cp.async 16B, L1-bypass
__device__ __forceinline__ void cp16(uint32_t dst, const void* src) {
    asm volatile("cp.async.cg.shared.global [%0], [%1], 16;"
                 :: "r"(dst), "l"(src) : "memory");
}
__device__ __forceinline__ void cp_commit() {
    asm volatile("cp.async.commit_group;" ::: "memory");
}
template <int N>
__device__ __forceinline__ void cp_wait() {
    asm volatile("cp.async.wait_group %0;" :: "n"(N) : "memory");
}

// ---------------- warp MMA primitives --------------------------------------
__device__ __forceinline__ void ldm_x4(uint32_t* f, uint32_t addr) {
    asm volatile("ldmatrix.sync.aligned.m8n8.x4.shared.b16 {%0,%1,%2,%3}, [%4];"
                 : "=r"(f[0]), "=r"(f[1]), "=r"(f[2]), "=r"(f[3]) : "r"(addr));
}
__device__ __forceinline__ void ldm_x2(uint32_t* f, uint32_t addr) {
    asm volatile("ldmatrix.sync.aligned.m8n8.x2.shared.b16 {%0,%1}, [%2];"
                 : "=r"(f[0]), "=r"(f[1]) : "r"(addr));
}
__device__ __forceinline__ void ldm_x2t(uint32_t* f, uint32_t addr) {
    asm volatile("ldmatrix.sync.aligned.m8n8.x2.trans.shared.b16 {%0,%1}, [%2];"
                 : "=r"(f[0]), "=r"(f[1]) : "r"(addr));
}
__device__ __forceinline__ void mma_bf16(float* c, const uint32_t* a, const uint32_t* b) {
    asm volatile(
        "mma.sync.aligned.m16n8k16.row.col.f32.bf16.bf16.f32 "
        "{%0,%1,%2,%3}, {%4,%5,%6,%7}, {%8,%9}, {%0,%1,%2,%3};"
        : "+f"(c[0]), "+f"(c[1]), "+f"(c[2]), "+f"(c[3])
        : "r"(a[0]), "r"(a[1]), "r"(a[2]), "r"(a[3]), "r"(b[0]), "r"(b[1]));
}

// ---------------- scratch ---------------------------------------------------
__device__ bf16 g_wh[4 * D_MODEL * D_MODEL];
__device__ bf16 g_wl[4 * D_MODEL * D_MODEL];
__device__ bf16 g_xh[3 * NTOK * D_MODEL];   // input splits; slot0 reused for O splits
__device__ bf16 g_xl[3 * NTOK * D_MODEL];
__device__ bf16 g_yh[3 * NTOK * D_MODEL];   // q/k/v splits (q pre-scaled)
__device__ bf16 g_yl[3 * NTOK * D_MODEL];

// ---------------- weight build + bf16 split --------------------------------
__global__ void wsplit_kernel(const float* __restrict__ Wq, const float* __restrict__ Aq,
                              const float* __restrict__ Wk, const float* __restrict__ Ak,
                              const float* __restrict__ Wv, const float* __restrict__ Av,
                              const float* __restrict__ Wo,
                              bf16* __restrict__ wh, bf16* __restrict__ wl) {
    int which = blockIdx.y;
    const float* W = (which == 0) ? Wq : (which == 1) ? Wk : (which == 2) ? Wv : Wo;
    const float* A = (which == 0) ? Aq : (which == 1) ? Ak : Av;
    int idx = blockIdx.x * blockDim.x + threadIdx.x;
    if (idx >= D_MODEL * D_MODEL) return;
    int n = idx / D_MODEL;
    int k = idx - n * D_MODEL;
    float acc = W[idx];
    if (which < 3) {
        float s = 0.0f;
#pragma unroll
        for (int r = 0; r < LORA_R; r++)
            s += A[n * LORA_R + r] * A[k * LORA_R + r];
        acc += LORA_SCALE * s;
    }
    bf16 h = __float2bfloat16(acc);
    bf16 l = __float2bfloat16(acc - __bfloat162float(h));
    size_t o = (size_t)which * D_MODEL * D_MODEL + idx;
    wh[o] = h;
    wl[o] = l;
}

// ---------------- activation bf16 split ------------------------------------
__global__ void xsplit_kernel(const float* __restrict__ x0,
                              const float* __restrict__ x1,
                              const float* __restrict__ x2,
                              bf16* __restrict__ h, bf16* __restrict__ l) {
    int z = blockIdx.z;
    const float* x = (z == 0) ? x0 : (z == 1) ? x1 : x2;
    size_t i = ((size_t)blockIdx.x * blockDim.x + threadIdx.x) * 4;
    if (i >= (size_t)NTOK * D_MODEL) return;
    size_t o = (size_t)z * NTOK * D_MODEL + i;
    float4 v = *reinterpret_cast<const float4*>(&x[i]);
    *reinterpret_cast<uint32_t*>(&h[o])     = prmt_hi(v.x, v.y);
    *reinterpret_cast<uint32_t*>(&h[o + 2]) = prmt_hi(v.z, v.w);
    *reinterpret_cast<uint32_t*>(&l[o])     = cvt2bf(v.x - truncbf(v.x), v.y - truncbf(v.y));
    *reinterpret_cast<uint32_t*>(&l[o + 2]) = cvt2bf(v.z - truncbf(v.z), v.w - truncbf(v.w));
}

// ---------------- warp-MMA GEMM, cp.async double-buffered ------------------
// 128x128 tile, BK=32, 8 warps (2m x 4n), m16n8k16 bf16, 3-term split.
// dynamic smem: 2 stages x 32KB (Ah 8K | Al 8K | Bh 8K | Bl 8K)
#define GSTG 32768
#define GEMM_SMEM (2 * GSTG)

__global__ __launch_bounds__(256) void tgemm_kernel(
    const bf16* __restrict__ Xh_, const bf16* __restrict__ Xl_,
    const bf16* __restrict__ Wh_, const bf16* __restrict__ Wl_,
    const float* B0, const float* B1, const float* B2,
    float* __restrict__ Yf,
    bf16* __restrict__ Yh_, bf16* __restrict__ Yl_,
    float qscale) {
    extern __shared__ char smem[];
    uint32_t sb = smem_u32(smem);

    int z = blockIdx.z;
    const bf16* Xh = Xh_ + (size_t)z * NTOK * D_MODEL;
    const bf16* Xl = Xl_ + (size_t)z * NTOK * D_MODEL;
    const bf16* Wh = Wh_ + (size_t)z * D_MODEL * D_MODEL;
    const bf16* Wl = Wl_ + (size_t)z * D_MODEL * D_MODEL;
    const float* bias = (z == 0) ? B0 : (z == 1) ? B1 : B2;
    float ss = (z == 0) ? qscale : 1.0f;

    int tid = threadIdx.x;
    int lane = tid & 31, wid = tid >> 5;
    int wm = wid >> 2, wn = wid & 3;
    int brow = blockIdx.y * 128;
    int bcol = blockIdx.x * 128;

    // loader mapping: row = tid>>1 (0..127), half = tid&1 → two 16B chunks
    int row = tid >> 1, half = tid & 1;
    uint32_t swr = (uint32_t)((row >> 1) & 3);
    uint32_t so0 = (uint32_t)row * 64u + ((((uint32_t)half * 2u) ^ swr) << 4);
    uint32_t so1 = (uint32_t)row * 64u + ((((uint32_t)half * 2u + 1u) ^ swr) << 4);
    const bf16* gAh = Xh + (size_t)(brow + row) * D_MODEL + half * 16;
    const bf16* gAl = Xl + (size_t)(brow + row) * D_MODEL + half * 16;
    const bf16* gBh = Wh + (size_t)(bcol + row) * D_MODEL + half * 16;
    const bf16* gBl = Wl + (size_t)(bcol + row) * D_MODEL + half * 16;

    auto issue = [&](int stg, int k0) {
        uint32_t s = sb + stg * GSTG;
        cp16(s + so0,          gAh + k0);
        cp16(s + so1,          gAh + k0 + 8);
        cp16(s + 8192 + so0,   gAl + k0);
        cp16(s + 8192 + so1,   gAl + k0 + 8);
        cp16(s + 16384 + so0,  gBh + k0);
        cp16(s + 16384 + so1,  gBh + k0 + 8);
        cp16(s + 24576 + so0,  gBl + k0);
        cp16(s + 24576 + so1,  gBl + k0 + 8);
        cp_commit();
    };

    int l15 = lane & 15;
    uint32_t csA = (uint32_t)(lane >> 4);
    uint32_t csB = (uint32_t)((lane >> 3) & 1);
    uint32_t aRowA[4], swA[4];
#pragma unroll
    for (int mi = 0; mi < 4; mi++) {
        int r = wm * 64 + mi * 16 + l15;
        aRowA[mi] = (uint32_t)r * 64u;
        swA[mi] = (uint32_t)((r >> 1) & 3);
    }
    uint32_t aRowB[4], swB[4];
#pragma unroll
    for (int ni = 0; ni < 4; ni++) {
        int r = wn * 32 + ni * 8 + (lane & 7);
        aRowB[ni] = (uint32_t)r * 64u;
        swB[ni] = (uint32_t)((r >> 1) & 3);
    }

    float acc[4][4][4];
#pragma unroll
    for (int mi = 0; mi < 4; mi++)
#pragma unroll
        for (int ni = 0; ni < 4; ni++)
#pragma unroll
            for (int c = 0; c < 4; c++) acc[mi][ni][c] = 0.0f;

    issue(0, 0);

    const int NKC = D_MODEL / 32;   // 24
    for (int kc = 0; kc < NKC; kc++) {
        int buf = kc & 1;
        if (kc + 1 < NKC) {
            issue(buf ^ 1, (kc + 1) * 32);
            cp_wait<1>();
        } else {
            cp_wait<0>();
        }
        __syncthreads();

        uint32_t aAh = sb + buf * GSTG;
        uint32_t aAl = aAh + 8192;
        uint32_t aBh = aAh + 16384;
        uint32_t aBl = aAh + 24576;
#pragma unroll
        for (int ks = 0; ks < 2; ks++) {
            uint32_t kchA = (uint32_t)ks * 2u + csA;
            uint32_t kchB = (uint32_t)ks * 2u + csB;
            uint32_t ah[4][4], bh[4][2], bl[4][2];
#pragma unroll
            for (int mi = 0; mi < 4; mi++)
                ldm_x4(ah[mi], aAh + aRowA[mi] + (((kchA ^ swA[mi])) << 4));
#pragma unroll
            for (int ni = 0; ni < 4; ni++) {
                ldm_x2(bh[ni], aBh + aRowB[ni] + (((kchB ^ swB[ni])) << 4));
                ldm_x2(bl[ni], aBl + aRowB[ni] + (((kchB ^ swB[ni])) << 4));
            }
#pragma unroll
            for (int mi = 0; mi < 4; mi++)
#pragma unroll
                for (int ni = 0; ni < 4; ni++) {
                    mma_bf16(acc[mi][ni], ah[mi], bh[ni]);
                    mma_bf16(acc[mi][ni], ah[mi], bl[ni]);
                }
            uint32_t al[4][4];
#pragma unroll
            for (int mi = 0; mi < 4; mi++)
                ldm_x4(al[mi], aAl + aRowA[mi] + (((kchA ^ swA[mi])) << 4));
#pragma unroll
            for (int mi = 0; mi < 4; mi++)
#pragma unroll
                for (int ni = 0; ni < 4; ni++)
                    mma_bf16(acc[mi][ni], al[mi], bh[ni]);
        }
        __syncthreads();
    }

    bf16* Yh = Yh_ ? Yh_ + (size_t)z * NTOK * D_MODEL : nullptr;
    bf16* Yl = Yl_ ? Yl_ + (size_t)z * NTOK * D_MODEL : nullptr;

    int g = lane >> 2, t = lane & 3;
#pragma unroll
    for (int ni = 0; ni < 4; ni++) {
        int gcol = bcol + wn * 32 + ni * 8 + 2 * t;
        float2 b2 = *reinterpret_cast<const float2*>(&bias[gcol]);
#pragma unroll
        for (int mi = 0; mi < 4; mi++) {
            size_t grow = brow + wm * 64 + mi * 16 + g;
            float y0 = acc[mi][ni][0] + b2.x, y1 = acc[mi][ni][1] + b2.y;
            float y2 = acc[mi][ni][2] + b2.x, y3 = acc[mi][ni][3] + b2.y;
            if (Yf) {
                *reinterpret_cast<float2*>(&Yf[grow * D_MODEL + gcol]) =
                    make_float2(y0, y1);
                *reinterpret_cast<float2*>(&Yf[(grow + 8) * D_MODEL + gcol]) =
                    make_float2(y2, y3);
            }
            if (Yh) {
                float s0 = y0 * ss, s1 = y1 * ss, s2 = y2 * ss, s3 = y3 * ss;
                *reinterpret_cast<uint32_t*>(&Yh[grow * D_MODEL + gcol]) =
                    prmt_hi(s0, s1);
                *reinterpret_cast<uint32_t*>(&Yl[grow * D_MODEL + gcol]) =
                    cvt2bf(s0 - truncbf(s0), s1 - truncbf(s1));
                *reinterpret_cast<uint32_t*>(&Yh[(grow + 8) * D_MODEL + gcol]) =
                    prmt_hi(s2, s3);
                *reinterpret_cast<uint32_t*>(&Yl[(grow + 8) * D_MODEL + gcol]) =
                    cvt2bf(s2 - truncbf(s2), s3 - truncbf(s3));
            }
        }
    }
}

// ---------------- attention: tensor-core flash, cp.async pipelined ---------
// 8 warps x 16 query rows, 128q x 64k tiles. dynamic smem: 2 stages x 32KB
// (Kh 8K | Kl 8K | Vh 8K | Vl 8K); Q staged into stage1 during prologue.
#define ASTG 32768
#define ATT_SMEM (2 * ASTG)

__global__ __launch_bounds__(256, 2) void attn_kernel(
    const bf16* __restrict__ qh_, const bf16* __restrict__ ql_,
    const bf16* __restrict__ kh_, const bf16* __restrict__ kl_,
    const bf16* __restrict__ vh_, const bf16* __restrict__ vl_,
    bf16* __restrict__ oh_, bf16* __restrict__ ol_) {
    extern __shared__ char smem[];
    uint32_t sb = smem_u32(smem);

    int tid = threadIdx.x;
    int lane = tid & 31, wid = tid >> 5;
    int qt = blockIdx.x;
    int bh = blockIdx.y;
    int b = bh / NHEAD, h = bh - b * NHEAD;
    size_t base = (size_t)b * SEQ * D_MODEL + (size_t)h * 64;

    // KV tile loader (cp.async, one commit group per tile)
    auto issue_kv = [&](int stg, int kt) {
        uint32_t s = sb + stg * ASTG;
#pragma unroll
        for (int i = 0; i < 8; i++) {
            int idx = tid + 256 * i;            // 0..2047
            int tsel = idx >> 9;                // 0..3: Kh,Kl,Vh,Vl
            int li = idx & 511;
            int r = li >> 3, c = li & 7;
            const bf16* src = (tsel == 0) ? kh_ : (tsel == 1) ? kl_
                            : (tsel == 2) ? vh_ : vl_;
            cp16(s + tsel * 8192 + r * 128 + (((c ^ (r & 7))) << 4),
                 src + base + (size_t)(kt + r) * D_MODEL + c * 8);
        }
        cp_commit();
    };

    // prologue: stage Q into stage1 (G0), KV tile 0 into stage0 (G1)
#pragma unroll
    for (int i = 0; i < 8; i++) {
        int idx = tid + 256 * i;
        const bf16* src = (idx < 1024) ? qh_ : ql_;
        int li = idx & 1023;
        int r = li >> 3, c = li & 7;
        cp16(sb + ASTG + ((idx < 1024) ? 0 : 16384) +
                 r * 128 + (((c ^ (r & 7))) << 4),
             src + base + (size_t)(qt * 128 + r) * D_MODEL + c * 8);
    }
    cp_commit();
    issue_kv(0, 0);

    cp_wait<1>();          // Q ready
    __syncthreads();
    uint32_t fqh[4][4], fql[4][4];
    {
        int l15 = lane & 15, lhi = lane >> 4;
        int r = wid * 16 + l15;
#pragma unroll
        for (int kk = 0; kk < 4; kk++) {
            uint32_t ad = sb + ASTG + r * 128 + ((((2 * kk + lhi) ^ (r & 7))) << 4);
            ldm_x4(fqh[kk], ad);
            ldm_x4(fql[kk], ad + 16384);
        }
    }
    __syncthreads();       // everyone done reading Q before tile1 overwrites stage1

    float m0 = -1e30f, m1 = -1e30f, l0 = 0.0f, l1 = 0.0f;
    float o[8][4];
#pragma unroll
    for (int j = 0; j < 8; j++)
#pragma unroll
        for (int c = 0; c < 4; c++) o[j][c] = 0.0f;

    int bl8 = lane & 7, bsel = (lane >> 3) & 1;

    for (int kt = 0; kt < SEQ; kt += 64) {
        int buf = (kt >> 6) & 1;
        if (kt + 64 < SEQ) {
            issue_kv(buf ^ 1, kt + 64);
            cp_wait<1>();
        } else {
            cp_wait<0>();
        }
        __syncthreads();
        uint32_t stg = sb + buf * ASTG;

        // S = Q K^T
        float s[8][4];
#pragma unroll
        for (int j = 0; j < 8; j++)
#pragma unroll
            for (int c = 0; c < 4; c++) s[j][c] = 0.0f;
#pragma unroll
        for (int kk = 0; kk < 4; kk++) {
#pragma unroll
            for (int j = 0; j < 8; j++) {
                int br = 8 * j + bl8;
                uint32_t ad = stg + br * 128 + ((((2 * kk + bsel) ^ (br & 7))) << 4);
                uint32_t khf[2], klf[2];
                ldm_x2(khf, ad);
                mma_bf16(s[j], fqh[kk], khf);
                mma_bf16(s[j], fql[kk], khf);
                ldm_x2(klf, ad + 8192);
                mma_bf16(s[j], fqh[kk], klf);
            }
        }

        // online softmax (rows g, g+8)
        float rmax0 = s[0][0], rmax1 = s[0][2];
#pragma unroll
        for (int j = 0; j < 8; j++) {
            rmax0 = fmaxf(rmax0, fmaxf(s[j][0], s[j][1]));
            rmax1 = fmaxf(rmax1, fmaxf(s[j][2], s[j][3]));
        }
        rmax0 = fmaxf(rmax0, __shfl_xor_sync(0xffffffffu, rmax0, 1));
        rmax0 = fmaxf(rmax0, __shfl_xor_sync(0xffffffffu, rmax0, 2));
        rmax1 = fmaxf(rmax1, __shfl_xor_sync(0xffffffffu, rmax1, 1));
        rmax1 = fmaxf(rmax1, __shfl_xor_sync(0xffffffffu, rmax1, 2));
        float nm0 = fmaxf(m0, rmax0), nm1 = fmaxf(m1, rmax1);
        float a0 = fexp2(m0 - nm0), a1 = fexp2(m1 - nm1);
        m0 = nm0; m1 = nm1;
        float rs0 = 0.0f, rs1 = 0.0f;
#pragma unroll
        for (int j = 0; j < 8; j++) {
            s[j][0] = fexp2(s[j][0] - nm0);
            s[j][1] = fexp2(s[j][1] - nm0);
            s[j][2] = fexp2(s[j][2] - nm1);
            s[j][3] = fexp2(s[j][3] - nm1);
            rs0 += s[j][0] + s[j][1];
            rs1 += s[j][2] + s[j][3];
        }
        rs0 += __shfl_xor_sync(0xffffffffu, rs0, 1);
        rs0 += __shfl_xor_sync(0xffffffffu, rs0, 2);
        rs1 += __shfl_xor_sync(0xffffffffu, rs1, 1);
        rs1 += __shfl_xor_sync(0xffffffffu, rs1, 2);
        l0 = l0 * a0 + rs0;
        l1 = l1 * a1 + rs1;
#pragma unroll
        for (int j = 0; j < 8; j++) {
            o[j][0] *= a0; o[j][1] *= a0;
            o[j][2] *= a1; o[j][3] *= a1;
        }

        // PV
#pragma unroll
        for (int kk = 0; kk < 4; kk++) {
            int j0 = 2 * kk, j1 = 2 * kk + 1;
            uint32_t ph[4], pl[4];
            ph[0] = prmt_hi(s[j0][0], s[j0][1]);
            ph[1] = prmt_hi(s[j0][2], s[j0][3]);
            ph[2] = prmt_hi(s[j1][0], s[j1][1]);
            ph[3] = prmt_hi(s[j1][2], s[j1][3]);
            pl[0] = cvt2bf(s[j0][0] - truncbf(s[j0][0]), s[j0][1] - truncbf(s[j0][1]));
            pl[1] = cvt2bf(s[j0][2] - truncbf(s[j0][2]), s[j0][3] - truncbf(s[j0][3]));
            pl[2] = cvt2bf(s[j1][0] - truncbf(s[j1][0]), s[j1][1] - truncbf(s[j1][1]));
            pl[3] = cvt2bf(s[j1][2] - truncbf(s[j1][2]), s[j1][3] - truncbf(s[j1][3]));
            int vr = 16 * kk + bl8 + 8 * bsel;
#pragma unroll
            for (int j = 0; j < 8; j++) {
                uint32_t ad = stg + 16384 + vr * 128 + (((j ^ (vr & 7))) << 4);
                uint32_t vhf[2], vlf[2];
                ldm_x2t(vhf, ad);
                mma_bf16(o[j], ph, vhf);
                mma_bf16(o[j], pl, vhf);
                ldm_x2t(vlf, ad + 8192);
                mma_bf16(o[j], ph, vlf);
            }
        }
        __syncthreads();
    }

    // epilogue: O / l, write bf16 hi/lo splits
    float il0 = 1.0f / l0, il1 = 1.0f / l1;
    int g = lane >> 2, t2 = (lane & 3) * 2;
    size_t tok0 = (size_t)b * SEQ + qt * 128 + wid * 16 + g;
    size_t tok1 = tok0 + 8;
    int colbase = h * 64 + t2;
#pragma unroll
    for (int j = 0; j < 8; j++) {
        int col = colbase + 8 * j;
        float x0 = o[j][0] * il0, x1 = o[j][1] * il0;
        float x2 = o[j][2] * il1, x3 = o[j][3] * il1;
        *reinterpret_cast<uint32_t*>(&oh_[tok0 * D_MODEL + col]) = prmt_hi(x0, x1);
        *reinterpret_cast<uint32_t*>(&ol_[tok0 * D_MODEL + col]) =
            cvt2bf(x0 - truncbf(x0), x1 - truncbf(x1));
        *reinterpret_cast<uint32_t*>(&oh_[tok1 * D_MODEL + col]) = prmt_hi(x2, x3);
        *reinterpret_cast<uint32_t*>(&ol_[tok1 * D_MODEL + col]) =
            cvt2bf(x2 - truncbf(x2), x3 - truncbf(x3));
    }
}

// ---------------- launch ---------------------------------------------------
extern "C" void kernel_launch(void* const* d_in, const int* in_sizes, int n_in,
                              void* d_out, int out_size) {
    const float* query = (const float*)d_in[0];
    const float* key_  = (const float*)d_in[1];
    const float* value = (const float*)d_in[2];
    const float* Wq = (const float*)d_in[3];
    const float* bq = (const float*)d_in[4];
    const float* Aq = (const float*)d_in[5];
    const float* Wk = (const float*)d_in[6];
    const float* bk = (const float*)d_in[7];
    const float* Ak = (const float*)d_in[8];
    const float* Wv = (const float*)d_in[9];
    const float* bv = (const float*)d_in[10];
    const float* Av = (const float*)d_in[11];
    const float* Wo = (const float*)d_in[12];
    const float* bo = (const float*)d_in[13];
    float* out = (float*)d_out;

    bf16 *pwh, *pwl, *pxh, *pxl, *pyh, *pyl;
    cudaGetSymbolAddress((void**)&pwh, g_wh);
    cudaGetSymbolAddress((void**)&pwl, g_wl);
    cudaGetSymbolAddress((void**)&pxh, g_xh);
    cudaGetSymbolAddress((void**)&pxl, g_xl);
    cudaGetSymbolAddress((void**)&pyh, g_yh);
    cudaGetSymbolAddress((void**)&pyl, g_yl);

    size_t nw = D_MODEL * D_MODEL;
    size_t ntd = (size_t)NTOK * D_MODEL;

    cudaFuncSetAttribute(tgemm_kernel,
                         cudaFuncAttributeMaxDynamicSharedMemorySize, GEMM_SMEM);
    cudaFuncSetAttribute(attn_kernel,
                         cudaFuncAttributeMaxDynamicSharedMemorySize, ATT_SMEM);

    // #0: weight build + bf16 split
    dim3 wgrid((int)((nw + 255) / 256), 4);
    wsplit_kernel<<<wgrid, 256>>>(Wq, Aq, Wk, Ak, Wv, Av, Wo, pwh, pwl);

    // #1: split q/k/v inputs
    int nx = NTOK * D_MODEL / 4;
    dim3 xgrid((nx + 255) / 256, 1, 3);
    xsplit_kernel<<<xgrid, 256>>>(query, key_, value, pxh, pxl);

    // #2: qkv projections -> bf16 splits (q scaled by QSCALE)
    dim3 ggrid(D_MODEL / 128, NTOK / 128, 3);
    tgemm_kernel<<<ggrid, 256, GEMM_SMEM>>>(pxh, pxl, pwh, pwl, bq, bk, bv,
                                            nullptr, pyh, pyl, QSCALE);

    // #3: attention (profiled slot) -> O splits
    dim3 agrid(SEQ / 128, 2 * NHEAD);
    attn_kernel<<<agrid, 256, ATT_SMEM>>>(pyh, pyl,
                                          pyh + ntd, pyl + ntd,
                                          pyh + 2 * ntd, pyl + 2 * ntd,
                                          pxh, pxl);

    // #4: output projection (weight slot 3) -> fp32 out
    dim3 ogrid(D_MODEL / 128, NTOK / 128, 1);
    tgemm_kernel<<<ogrid, 256, GEMM_SMEM>>>(pxh, pxl, pwh + 3 * nw, pwl + 3 * nw,
                                            bo, bo, bo, out, nullptr, nullptr, 1.0f);
}

// round 11
// speedup vs baseline: 5.6829x; 1.0800x over previous
#include <cuda_runtime.h>
#include <cuda_bf16.h>
#include <cstdint>

#define D_MODEL 768
#define NTOK 4096           // B*S = 2*2048
#define SEQ 2048
#define NHEAD 12
#define LORA_R 16
#define LORA_SCALE 4.0f
#define QSCALE (0.125f * 1.4426950408889634f)   // 1/sqrt(64) * log2(e)

typedef __nv_bfloat16 bf16;

// ---------------- helpers ---------------------------------------------------
__device__ __forceinline__ float fexp2(float x) {
    float r;
    asm("ex2.approx.ftz.f32 %0, %1;" : "=f"(r) : "f"(x));
    return r;
}
__device__ __forceinline__ uint32_t smem_u32(const void* p) {
    uint32_t a;
    asm("{ .reg .u64 t; cvta.to.shared.u64 t, %1; cvt.u32.u64 %0, t; }"
        : "=r"(a) : "l"(p));
    return a;
}
__device__ __forceinline__ uint32_t prmt_hi(float a, float b) {
    uint32_t r;
    asm("prmt.b32 %0, %1, %2, 0x7632;" : "=r"(r)
        : "r"(__float_as_uint(a)), "r"(__float_as_uint(b)));
    return r;
}
__device__ __forceinline__ float truncbf(float a) {
    return __uint_as_float(__float_as_uint(a) & 0xFFFF0000u);
}
__device__ __forceinline__ uint32_t cvt2bf(float lo, float hi) {
    uint32_t r;
    asm("cvt.rn.bf16x2.f32 %0, %1, %2;" : "=r"(r) : "f"(hi), "f"(lo));
    return r;
}
__device__ __forceinline__ void cp16(uint32_t dst, const void* src) {
    asm volatile("cp.async.cg.shared.global [%0], [%1], 16;"
                 :: "r"(dst), "l"(src) : "memory");
}
__device__ __forceinline__ void cp_commit() {
    asm volatile("cp.async.commit_group;" ::: "memory");
}
template <int N>
__device__ __forceinline__ void cp_wait() {
    asm volatile("cp.async.wait_group %0;" :: "n"(N) : "memory");
}

// ---------------- warp MMA primitives --------------------------------------
__device__ __forceinline__ void ldm_x4(uint32_t* f, uint32_t addr) {
    asm volatile("ldmatrix.sync.aligned.m8n8.x4.shared.b16 {%0,%1,%2,%3}, [%4];"
                 : "=r"(f[0]), "=r"(f[1]), "=r"(f[2]), "=r"(f[3]) : "r"(addr));
}
__device__ __forceinline__ void ldm_x4t(uint32_t* f, uint32_t addr) {
    asm volatile("ldmatrix.sync.aligned.m8n8.x4.trans.shared.b16 {%0,%1,%2,%3}, [%4];"
                 : "=r"(f[0]), "=r"(f[1]), "=r"(f[2]), "=r"(f[3]) : "r"(addr));
}
__device__ __forceinline__ void mma_bf16(float* c, const uint32_t* a, const uint32_t* b) {
    asm volatile(
        "mma.sync.aligned.m16n8k16.row.col.f32.bf16.bf16.f32 "
        "{%0,%1,%2,%3}, {%4,%5,%6,%7}, {%8,%9}, {%0,%1,%2,%3};"
        : "+f"(c[0]), "+f"(c[1]), "+f"(c[2]), "+f"(c[3])
        : "r"(a[0]), "r"(a[1]), "r"(a[2]), "r"(a[3]), "r"(b[0]), "r"(b[1]));
}

// ---------------- scratch ---------------------------------------------------
__device__ bf16 g_wh[4 * D_MODEL * D_MODEL];
__device__ bf16 g_wl[4 * D_MODEL * D_MODEL];
__device__ bf16 g_xh[3 * NTOK * D_MODEL];   // input splits; slot0 reused for O splits
__device__ bf16 g_xl[3 * NTOK * D_MODEL];
__device__ bf16 g_yh[3 * NTOK * D_MODEL];   // q/k/v splits (q pre-scaled)
__device__ bf16 g_yl[3 * NTOK * D_MODEL];

// ---------------- weight build + bf16 split --------------------------------
__global__ void wsplit_kernel(const float* __restrict__ Wq, const float* __restrict__ Aq,
                              const float* __restrict__ Wk, const float* __restrict__ Ak,
                              const float* __restrict__ Wv, const float* __restrict__ Av,
                              const float* __restrict__ Wo,
                              bf16* __restrict__ wh, bf16* __restrict__ wl) {
    int which = blockIdx.y;
    const float* W = (which == 0) ? Wq : (which == 1) ? Wk : (which == 2) ? Wv : Wo;
    const float* A = (which == 0) ? Aq : (which == 1) ? Ak : Av;
    int idx = blockIdx.x * blockDim.x + threadIdx.x;
    if (idx >= D_MODEL * D_MODEL) return;
    int n = idx / D_MODEL;
    int k = idx - n * D_MODEL;
    float acc = W[idx];
    if (which < 3) {
        float s = 0.0f;
#pragma unroll
        for (int r = 0; r < LORA_R; r++)
            s += A[n * LORA_R + r] * A[k * LORA_R + r];
        acc += LORA_SCALE * s;
    }
    bf16 h = __float2bfloat16(acc);
    bf16 l = __float2bfloat16(acc - __bfloat162float(h));
    size_t o = (size_t)which * D_MODEL * D_MODEL + idx;
    wh[o] = h;
    wl[o] = l;
}

// ---------------- activation bf16 split ------------------------------------
__global__ void xsplit_kernel(const float* __restrict__ x0,
                              const float* __restrict__ x1,
                              const float* __restrict__ x2,
                              bf16* __restrict__ h, bf16* __restrict__ l) {
    int z = blockIdx.z;
    const float* x = (z == 0) ? x0 : (z == 1) ? x1 : x2;
    size_t i = ((size_t)blockIdx.x * blockDim.x + threadIdx.x) * 4;
    if (i >= (size_t)NTOK * D_MODEL) return;
    size_t o = (size_t)z * NTOK * D_MODEL + i;
    float4 v = *reinterpret_cast<const float4*>(&x[i]);
    *reinterpret_cast<uint32_t*>(&h[o])     = prmt_hi(v.x, v.y);
    *reinterpret_cast<uint32_t*>(&h[o + 2]) = prmt_hi(v.z, v.w);
    *reinterpret_cast<uint32_t*>(&l[o])     = cvt2bf(v.x - truncbf(v.x), v.y - truncbf(v.y));
    *reinterpret_cast<uint32_t*>(&l[o + 2]) = cvt2bf(v.z - truncbf(v.z), v.w - truncbf(v.w));
}

// ---------------- warp-MMA GEMM, cp.async 2-stage, 1 barrier/iter ----------
#define GSTG 32768
#define GEMM_SMEM (2 * GSTG)

__global__ __launch_bounds__(256) void tgemm_kernel(
    const bf16* __restrict__ Xh_, const bf16* __restrict__ Xl_,
    const bf16* __restrict__ Wh_, const bf16* __restrict__ Wl_,
    const float* B0, const float* B1, const float* B2,
    float* __restrict__ Yf,
    bf16* __restrict__ Yh_, bf16* __restrict__ Yl_,
    float qscale) {
    extern __shared__ char smem[];
    uint32_t sb = smem_u32(smem);

    int z = blockIdx.z;
    const bf16* Xh = Xh_ + (size_t)z * NTOK * D_MODEL;
    const bf16* Xl = Xl_ + (size_t)z * NTOK * D_MODEL;
    const bf16* Wh = Wh_ + (size_t)z * D_MODEL * D_MODEL;
    const bf16* Wl = Wl_ + (size_t)z * D_MODEL * D_MODEL;
    const float* bias = (z == 0) ? B0 : (z == 1) ? B1 : B2;
    float ss = (z == 0) ? qscale : 1.0f;

    int tid = threadIdx.x;
    int lane = tid & 31, wid = tid >> 5;
    int wm = wid >> 2, wn = wid & 3;
    int brow = blockIdx.y * 128;
    int bcol = blockIdx.x * 128;

    int row = tid >> 1, half = tid & 1;
    uint32_t swr = (uint32_t)((row >> 1) & 3);
    uint32_t so0 = (uint32_t)row * 64u + ((((uint32_t)half * 2u) ^ swr) << 4);
    uint32_t so1 = (uint32_t)row * 64u + ((((uint32_t)half * 2u + 1u) ^ swr) << 4);
    const bf16* gAh = Xh + (size_t)(brow + row) * D_MODEL + half * 16;
    const bf16* gAl = Xl + (size_t)(brow + row) * D_MODEL + half * 16;
    const bf16* gBh = Wh + (size_t)(bcol + row) * D_MODEL + half * 16;
    const bf16* gBl = Wl + (size_t)(bcol + row) * D_MODEL + half * 16;

    auto issue = [&](int stg, int k0) {
        uint32_t s = sb + stg * GSTG;
        cp16(s + so0,          gAh + k0);
        cp16(s + so1,          gAh + k0 + 8);
        cp16(s + 8192 + so0,   gAl + k0);
        cp16(s + 8192 + so1,   gAl + k0 + 8);
        cp16(s + 16384 + so0,  gBh + k0);
        cp16(s + 16384 + so1,  gBh + k0 + 8);
        cp16(s + 24576 + so0,  gBl + k0);
        cp16(s + 24576 + so1,  gBl + k0 + 8);
        cp_commit();
    };

    int l15 = lane & 15;
    uint32_t csA = (uint32_t)(lane >> 4);
    uint32_t aRowA[4], swA[4];
#pragma unroll
    for (int mi = 0; mi < 4; mi++) {
        int r = wm * 64 + mi * 16 + l15;
        aRowA[mi] = (uint32_t)r * 64u;
        swA[mi] = (uint32_t)((r >> 1) & 3);
    }
    // B: x4 over ni pairs; lanes 16-31 address the ni+1 matrices
    uint32_t csB = (uint32_t)((lane >> 3) & 1);
    int brB = (lane & 7) | ((lane >> 1) & 8);
    uint32_t aRowB2[2], swB2[2];
#pragma unroll
    for (int p = 0; p < 2; p++) {
        int r = wn * 32 + p * 16 + brB;
        aRowB2[p] = (uint32_t)r * 64u;
        swB2[p] = (uint32_t)((r >> 1) & 3);
    }

    float acc[4][4][4];
#pragma unroll
    for (int mi = 0; mi < 4; mi++)
#pragma unroll
        for (int ni = 0; ni < 4; ni++)
#pragma unroll
            for (int c = 0; c < 4; c++) acc[mi][ni][c] = 0.0f;

    issue(0, 0);

    const int NKC = D_MODEL / 32;   // 24
    for (int kc = 0; kc < NKC; kc++) {
        int buf = kc & 1;
        cp_wait<0>();
        __syncthreads();
        if (kc + 1 < NKC) issue(buf ^ 1, (kc + 1) * 32);

        uint32_t aAh = sb + buf * GSTG;
        uint32_t aAl = aAh + 8192;
        uint32_t aBh = aAh + 16384;
        uint32_t aBl = aAh + 24576;
#pragma unroll
        for (int ks = 0; ks < 2; ks++) {
            uint32_t kchA = (uint32_t)ks * 2u + csA;
            uint32_t kchB = (uint32_t)ks * 2u + csB;
            uint32_t ah[4][4], b4h[2][4], b4l[2][4];
#pragma unroll
            for (int mi = 0; mi < 4; mi++)
                ldm_x4(ah[mi], aAh + aRowA[mi] + (((kchA ^ swA[mi])) << 4));
#pragma unroll
            for (int p = 0; p < 2; p++) {
                uint32_t off = aRowB2[p] + (((kchB ^ swB2[p])) << 4);
                ldm_x4(b4h[p], aBh + off);
                ldm_x4(b4l[p], aBl + off);
            }
#pragma unroll
            for (int mi = 0; mi < 4; mi++)
#pragma unroll
                for (int ni = 0; ni < 4; ni++) {
                    mma_bf16(acc[mi][ni], ah[mi], &b4h[ni >> 1][(ni & 1) * 2]);
                    mma_bf16(acc[mi][ni], ah[mi], &b4l[ni >> 1][(ni & 1) * 2]);
                }
            uint32_t al[4][4];
#pragma unroll
            for (int mi = 0; mi < 4; mi++)
                ldm_x4(al[mi], aAl + aRowA[mi] + (((kchA ^ swA[mi])) << 4));
#pragma unroll
            for (int mi = 0; mi < 4; mi++)
#pragma unroll
                for (int ni = 0; ni < 4; ni++)
                    mma_bf16(acc[mi][ni], al[mi], &b4h[ni >> 1][(ni & 1) * 2]);
        }
    }

    bf16* Yh = Yh_ ? Yh_ + (size_t)z * NTOK * D_MODEL : nullptr;
    bf16* Yl = Yl_ ? Yl_ + (size_t)z * NTOK * D_MODEL : nullptr;

    int g = lane >> 2, t = lane & 3;
#pragma unroll
    for (int ni = 0; ni < 4; ni++) {
        int gcol = bcol + wn * 32 + ni * 8 + 2 * t;
        float2 b2 = *reinterpret_cast<const float2*>(&bias[gcol]);
#pragma unroll
        for (int mi = 0; mi < 4; mi++) {
            size_t grow = brow + wm * 64 + mi * 16 + g;
            float y0 = acc[mi][ni][0] + b2.x, y1 = acc[mi][ni][1] + b2.y;
            float y2 = acc[mi][ni][2] + b2.x, y3 = acc[mi][ni][3] + b2.y;
            if (Yf) {
                *reinterpret_cast<float2*>(&Yf[grow * D_MODEL + gcol]) =
                    make_float2(y0, y1);
                *reinterpret_cast<float2*>(&Yf[(grow + 8) * D_MODEL + gcol]) =
                    make_float2(y2, y3);
            }
            if (Yh) {
                float s0 = y0 * ss, s1 = y1 * ss, s2 = y2 * ss, s3 = y3 * ss;
                *reinterpret_cast<uint32_t*>(&Yh[grow * D_MODEL + gcol]) =
                    prmt_hi(s0, s1);
                *reinterpret_cast<uint32_t*>(&Yl[grow * D_MODEL + gcol]) =
                    cvt2bf(s0 - truncbf(s0), s1 - truncbf(s1));
                *reinterpret_cast<uint32_t*>(&Yh[(grow + 8) * D_MODEL + gcol]) =
                    prmt_hi(s2, s3);
                *reinterpret_cast<uint32_t*>(&Yl[(grow + 8) * D_MODEL + gcol]) =
                    cvt2bf(s2 - truncbf(s2), s3 - truncbf(s3));
            }
        }
    }
}

// ---------------- attention: tensor-core flash, x4 ldmatrix, 1 barrier -----
#define ASTG 32768
#define ATT_SMEM (2 * ASTG)

__global__ __launch_bounds__(256, 2) void attn_kernel(
    const bf16* __restrict__ qh_, const bf16* __restrict__ ql_,
    const bf16* __restrict__ kh_, const bf16* __restrict__ kl_,
    const bf16* __restrict__ vh_, const bf16* __restrict__ vl_,
    bf16* __restrict__ oh_, bf16* __restrict__ ol_) {
    extern __shared__ char smem[];
    uint32_t sb = smem_u32(smem);

    int tid = threadIdx.x;
    int lane = tid & 31, wid = tid >> 5;
    int qt = blockIdx.x;
    int bh = blockIdx.y;
    int b = bh / NHEAD, h = bh - b * NHEAD;
    size_t base = (size_t)b * SEQ * D_MODEL + (size_t)h * 64;

    // hoisted per-thread loader state: idx = tid + 256*i → tsel = i>>1 (static)
    int lrow = (tid & 255) >> 3;       // row for even i; +32 for odd i
    int lcol = tid & 7;
    uint32_t d0 = (uint32_t)lrow * 128 + (((uint32_t)lcol ^ (lrow & 7)) << 4);
    int lrow1 = lrow + 32;
    uint32_t d1 = (uint32_t)lrow1 * 128 + (((uint32_t)lcol ^ (lrow1 & 7)) << 4);
    size_t rc0 = (size_t)lrow * D_MODEL + lcol * 8;
    const bf16* pkh = kh_ + base + rc0;
    const bf16* pkl = kl_ + base + rc0;
    const bf16* pvh = vh_ + base + rc0;
    const bf16* pvl = vl_ + base + rc0;

    auto issue_kv = [&](uint32_t s, size_t gofs) {
#pragma unroll
        for (int i = 0; i < 8; i++) {
            const bf16* p = ((i >> 1) == 0 ? pkh : (i >> 1) == 1 ? pkl
                           : (i >> 1) == 2 ? pvh : pvl)
                          + gofs + ((i & 1) ? 32 * D_MODEL : 0);
            cp16(s + (i >> 1) * 8192 + ((i & 1) ? d1 : d0), p);
        }
        cp_commit();
    };

    // prologue: stage Q into stage1 (G_Q), KV tile 0 into stage0 (G_0)
#pragma unroll
    for (int i = 0; i < 8; i++) {
        int idx = tid + 256 * i;
        const bf16* src = (idx < 1024) ? qh_ : ql_;
        int li = idx & 1023;
        int r = li >> 3, c = li & 7;
        cp16(sb + ASTG + ((idx < 1024) ? 0 : 16384) +
                 r * 128 + (((c ^ (r & 7))) << 4),
             src + base + (size_t)(qt * 128 + r) * D_MODEL + c * 8);
    }
    cp_commit();
    issue_kv(sb, 0);

    cp_wait<1>();          // Q ready
    __syncthreads();
    uint32_t fqh[4][4], fql[4][4];
    {
        int l15 = lane & 15, lhi = lane >> 4;
        int r = wid * 16 + l15;
#pragma unroll
        for (int kk = 0; kk < 4; kk++) {
            uint32_t ad = sb + ASTG + r * 128 + ((((2 * kk + lhi) ^ (r & 7))) << 4);
            ldm_x4(fqh[kk], ad);
            ldm_x4(fql[kk], ad + 16384);
        }
    }

    float m0 = -1e30f, m1 = -1e30f, l0 = 0.0f, l1 = 0.0f;
    float o[8][4];
#pragma unroll
    for (int j = 0; j < 8; j++)
#pragma unroll
        for (int c = 0; c < 4; c++) o[j][c] = 0.0f;

    // QK x4 lane addressing: lanes 16-31 address j+1's matrices
    int jrow = (lane & 7) | ((lane >> 1) & 8);
    int cs2 = (lane >> 3) & 1;
    // PV x4t: rows lane&15, lanes 16-31 take chunk j+1
    int vrow = lane & 15;
    int vchA = lane >> 4;

    for (int kt = 0; kt < SEQ; kt += 64) {
        int buf = (kt >> 6) & 1;
        cp_wait<0>();
        __syncthreads();    // data published + previous compute on buf^1 done
        if (kt + 64 < SEQ) issue_kv(sb + (buf ^ 1) * ASTG, (size_t)(kt + 64) * D_MODEL);
        uint32_t stg = sb + buf * ASTG;

        // S = Q K^T  (x4 loads serve j2 and j2+1)
        float s[8][4];
#pragma unroll
        for (int j = 0; j < 8; j++)
#pragma unroll
            for (int c = 0; c < 4; c++) s[j][c] = 0.0f;
#pragma unroll
        for (int kk = 0; kk < 4; kk++) {
#pragma unroll
            for (int j2 = 0; j2 < 8; j2 += 2) {
                int br = 8 * j2 + jrow;
                uint32_t ad = stg + br * 128 + ((((2 * kk + cs2) ^ (br & 7))) << 4);
                uint32_t kh4[4], kl4[4];
                ldm_x4(kh4, ad);
                ldm_x4(kl4, ad + 8192);
                mma_bf16(s[j2],     fqh[kk], &kh4[0]);
                mma_bf16(s[j2],     fql[kk], &kh4[0]);
                mma_bf16(s[j2],     fqh[kk], &kl4[0]);
                mma_bf16(s[j2 + 1], fqh[kk], &kh4[2]);
                mma_bf16(s[j2 + 1], fql[kk], &kh4[2]);
                mma_bf16(s[j2 + 1], fqh[kk], &kl4[2]);
            }
        }

        // online softmax (rows g, g+8)
        float rmax0 = s[0][0], rmax1 = s[0][2];
#pragma unroll
        for (int j = 0; j < 8; j++) {
            rmax0 = fmaxf(rmax0, fmaxf(s[j][0], s[j][1]));
            rmax1 = fmaxf(rmax1, fmaxf(s[j][2], s[j][3]));
        }
        rmax0 = fmaxf(rmax0, __shfl_xor_sync(0xffffffffu, rmax0, 1));
        rmax0 = fmaxf(rmax0, __shfl_xor_sync(0xffffffffu, rmax0, 2));
        rmax1 = fmaxf(rmax1, __shfl_xor_sync(0xffffffffu, rmax1, 1));
        rmax1 = fmaxf(rmax1, __shfl_xor_sync(0xffffffffu, rmax1, 2));
        float nm0 = fmaxf(m0, rmax0), nm1 = fmaxf(m1, rmax1);
        bool rescale = (nm0 != m0) || (nm1 != m1);
        float a0 = fexp2(m0 - nm0), a1 = fexp2(m1 - nm1);
        m0 = nm0; m1 = nm1;
        float rs0 = 0.0f, rs1 = 0.0f;
#pragma unroll
        for (int j = 0; j < 8; j++) {
            s[j][0] = fexp2(s[j][0] - nm0);
            s[j][1] = fexp2(s[j][1] - nm0);
            s[j][2] = fexp2(s[j][2] - nm1);
            s[j][3] = fexp2(s[j][3] - nm1);
            rs0 += s[j][0] + s[j][1];
            rs1 += s[j][2] + s[j][3];
        }
        rs0 += __shfl_xor_sync(0xffffffffu, rs0, 1);
        rs0 += __shfl_xor_sync(0xffffffffu, rs0, 2);
        rs1 += __shfl_xor_sync(0xffffffffu, rs1, 1);
        rs1 += __shfl_xor_sync(0xffffffffu, rs1, 2);
        l0 = l0 * a0 + rs0;
        l1 = l1 * a1 + rs1;
        if (__any_sync(0xffffffffu, rescale)) {
#pragma unroll
            for (int j = 0; j < 8; j++) {
                o[j][0] *= a0; o[j][1] *= a0;
                o[j][2] *= a1; o[j][3] *= a1;
            }
        }

        // PV: P fragments repacked in registers; x4t loads serve j2/j2+1
#pragma unroll
        for (int kk = 0; kk < 4; kk++) {
            int j0 = 2 * kk, j1 = 2 * kk + 1;
            uint32_t ph[4], pl[4];
            ph[0] = prmt_hi(s[j0][0], s[j0][1]);
            ph[1] = prmt_hi(s[j0][2], s[j0][3]);
            ph[2] = prmt_hi(s[j1][0], s[j1][1]);
            ph[3] = prmt_hi(s[j1][2], s[j1][3]);
            pl[0] = cvt2bf(s[j0][0] - truncbf(s[j0][0]), s[j0][1] - truncbf(s[j0][1]));
            pl[1] = cvt2bf(s[j0][2] - truncbf(s[j0][2]), s[j0][3] - truncbf(s[j0][3]));
            pl[2] = cvt2bf(s[j1][0] - truncbf(s[j1][0]), s[j1][1] - truncbf(s[j1][1]));
            pl[3] = cvt2bf(s[j1][2] - truncbf(s[j1][2]), s[j1][3] - truncbf(s[j1][3]));
            int vr = 16 * kk + vrow;
#pragma unroll
            for (int j2 = 0; j2 < 8; j2 += 2) {
                int ch = j2 + vchA;
                uint32_t ad = stg + 16384 + vr * 128 + (((ch ^ (vr & 7))) << 4);
                uint32_t vh4[4], vl4[4];
                ldm_x4t(vh4, ad);
                ldm_x4t(vl4, ad + 8192);
                mma_bf16(o[j2],     ph, &vh4[0]);
                mma_bf16(o[j2],     pl, &vh4[0]);
                mma_bf16(o[j2],     ph, &vl4[0]);
                mma_bf16(o[j2 + 1], ph, &vh4[2]);
                mma_bf16(o[j2 + 1], pl, &vh4[2]);
                mma_bf16(o[j2 + 1], ph, &vl4[2]);
            }
        }
    }

    // epilogue: O / l, write bf16 hi/lo splits
    float il0 = 1.0f / l0, il1 = 1.0f / l1;
    int g = lane >> 2, t2 = (lane & 3) * 2;
    size_t tok0 = (size_t)b * SEQ + qt * 128 + wid * 16 + g;
    size_t tok1 = tok0 + 8;
    int colbase = h * 64 + t2;
#pragma unroll
    for (int j = 0; j < 8; j++) {
        int col = colbase + 8 * j;
        float x0 = o[j][0] * il0, x1 = o[j][1] * il0;
        float x2 = o[j][2] * il1, x3 = o[j][3] * il1;
        *reinterpret_cast<uint32_t*>(&oh_[tok0 * D_MODEL + col]) = prmt_hi(x0, x1);
        *reinterpret_cast<uint32_t*>(&ol_[tok0 * D_MODEL + col]) =
            cvt2bf(x0 - truncbf(x0), x1 - truncbf(x1));
        *reinterpret_cast<uint32_t*>(&oh_[tok1 * D_MODEL + col]) = prmt_hi(x2, x3);
        *reinterpret_cast<uint32_t*>(&ol_[tok1 * D_MODEL + col]) =
            cvt2bf(x2 - truncbf(x2), x3 - truncbf(x3));
    }
}

// ---------------- launch ---------------------------------------------------
extern "C" void kernel_launch(void* const* d_in, const int* in_sizes, int n_in,
                              void* d_out, int out_size) {
    const float* query = (const float*)d_in[0];
    const float* key_  = (const float*)d_in[1];
    const float* value = (const float*)d_in[2];
    const float* Wq = (const float*)d_in[3];
    const float* bq = (const float*)d_in[4];
    const float* Aq = (const float*)d_in[5];
    const float* Wk = (const float*)d_in[6];
    const float* bk = (const float*)d_in[7];
    const float* Ak = (const float*)d_in[8];
    const float* Wv = (const float*)d_in[9];
    const float* bv = (const float*)d_in[10];
    const float* Av = (const float*)d_in[11];
    const float* Wo = (const float*)d_in[12];
    const float* bo = (const float*)d_in[13];
    float* out = (float*)d_out;

    bf16 *pwh, *pwl, *pxh, *pxl, *pyh, *pyl;
    cudaGetSymbolAddress((void**)&pwh, g_wh);
    cudaGetSymbolAddress((void**)&pwl, g_wl);
    cudaGetSymbolAddress((void**)&pxh, g_xh);
    cudaGetSymbolAddress((void**)&pxl, g_xl);
    cudaGetSymbolAddress((void**)&pyh, g_yh);
    cudaGetSymbolAddress((void**)&pyl, g_yl);

    size_t nw = D_MODEL * D_MODEL;
    size_t ntd = (size_t)NTOK * D_MODEL;

    cudaFuncSetAttribute(tgemm_kernel,
                         cudaFuncAttributeMaxDynamicSharedMemorySize, GEMM_SMEM);
    cudaFuncSetAttribute(attn_kernel,
                         cudaFuncAttributeMaxDynamicSharedMemorySize, ATT_SMEM);

    // #0: weight build + bf16 split
    dim3 wgrid((int)((nw + 255) / 256), 4);
    wsplit_kernel<<<wgrid, 256>>>(Wq, Aq, Wk, Ak, Wv, Av, Wo, pwh, pwl);

    // #1: split q/k/v inputs
    int nx = NTOK * D_MODEL / 4;
    dim3 xgrid((nx + 255) / 256, 1, 3);
    xsplit_kernel<<<xgrid, 256>>>(query, key_, value, pxh, pxl);

    // #2: qkv projections -> bf16 splits (q scaled by QSCALE)
    dim3 ggrid(D_MODEL / 128, NTOK / 128, 3);
    tgemm_kernel<<<ggrid, 256, GEMM_SMEM>>>(pxh, pxl, pwh, pwl, bq, bk, bv,
                                            nullptr, pyh, pyl, QSCALE);

    // #3: attention (profiled slot) -> O splits
    dim3 agrid(SEQ / 128, 2 * NHEAD);
    attn_kernel<<<agrid, 256, ATT_SMEM>>>(pyh, pyl,
                                          pyh + ntd, pyl + ntd,
                                          pyh + 2 * ntd, pyl + 2 * ntd,
                                          pxh, pxl);

    // #4: output projection (weight slot 3) -> fp32 out
    dim3 ogrid(D_MODEL / 128, NTOK / 128, 1);
    tgemm_kernel<<<ogrid, 256, GEMM_SMEM>>>(pxh, pxl, pwh + 3 * nw, pwl + 3 * nw,
                                            bo, bo, bo, out, nullptr, nullptr, 1.0f);
}